// round 6
// baseline (speedup 1.0000x reference)
#include <cuda_runtime.h>
#include <cstdint>
#include <math.h>

#define CC 1024
#define NROWS (256*1024)
#define RP1 260     // f1 transposed row pad (256 rows + 4)
#define XDP 260     // f2 duplicated-X row pitch (2*128 + 4)
#define HTP 132     // f2 plain ht row pitch (128 + 4)

typedef unsigned long long ull;

// Scratch (allocation-free rule: __device__ globals)
__device__ float g_adj[2*CC];
__device__ float g_kcbase[2*CC*64];                 // per-(k,c) folded kc@Wn1_kc + bn1
__device__ float g_mnext[(size_t)NROWS * 64];       // 64 MB intermediate m_next

// ---- packed f32x2 helpers -------------------------------------------------
__device__ __forceinline__ ull dup2(float x){ ull r; asm("mov.b64 %0,{%1,%1};":"=l"(r):"f"(x)); return r; }
__device__ __forceinline__ ull pk2(float lo, float hi){ ull r; asm("mov.b64 %0,{%1,%2};":"=l"(r):"f"(lo),"f"(hi)); return r; }
__device__ __forceinline__ float2 up2(ull v){ float2 f; asm("mov.b64 {%0,%1},%2;":"=f"(f.x),"=f"(f.y):"l"(v)); return f; }
__device__ __forceinline__ void fma2(ull&d, ull a, ull b){ asm("fma.rn.f32x2 %0,%1,%2,%0;":"+l"(d):"l"(a),"l"(b)); }

__device__ __forceinline__ float clampf(float v,float lo,float hi){ return fminf(fmaxf(v,lo),hi); }
__device__ __forceinline__ float sigf(float x){ return __fdividef(1.f, 1.f + __expf(-x)); }
__device__ __forceinline__ float tanhfast(float x){
    float t = __expf(-2.f*fabsf(x));
    float r = __fdividef(1.f - t, 1.f + t);
    return copysignf(r, x);
}

// ---------------------------------------------------------------------------
// adj: mask0 has ~5 nonzeros -> compact + gather
// ---------------------------------------------------------------------------
__global__ void adj_kernel(const int* __restrict__ qt,
                           const float* __restrict__ oh,
                           const float* __restrict__ graphs)
{
    __shared__ int   s_idx[CC];
    __shared__ float s_val[CC];
    __shared__ int   s_cnt;
    __shared__ float s_sum;

    int t = threadIdx.x;
    if (t == 0) { s_cnt = 0; s_sum = 0.f; }
    __syncthreads();

    int q0 = qt[0];
    float m = oh[(size_t)q0 * CC + t];
    if (m != 0.f) {
        int p = atomicAdd(&s_cnt, 1);
        s_idx[p] = t; s_val[p] = m;
        atomicAdd(&s_sum, m);
    }
    __syncthreads();

    float denom = fmaxf(s_sum, 1.f);
    int nnz = s_cnt;
    for (int k = 0; k < 2; k++) {
        float acc = 0.f;
        for (int i = 0; i < nnz; i++)
            acc += s_val[i] * graphs[(size_t)k*CC*CC + (size_t)s_idx[i]*CC + t];
        g_adj[k*CC + t] = clampf(acc / denom, -5.f, 5.f);
    }
}

// ---------------------------------------------------------------------------
// kcbase[k][c][j] = bn1[k][j] + sum_e clip(kc[c][e],±5) * Wn1[k][192+e][j]
// ---------------------------------------------------------------------------
__global__ void kcbase_kernel(const float* __restrict__ kc,
                              const float* __restrict__ Wn1,
                              const float* __restrict__ bn1)
{
    __shared__ float skc[64];
    int c = blockIdx.x;
    int tid = threadIdx.x;              // 128
    if (tid < 64) skc[tid] = clampf(kc[c*64 + tid], -5.f, 5.f);
    __syncthreads();
    int k = tid >> 6, j = tid & 63;
    float a = bn1[k*64 + j];
    const float* Wp = Wn1 + k*16384 + 12288 + j;   // rows 192..255 of Wn1[k]
    #pragma unroll 8
    for (int e = 0; e < 64; e++) a = fmaf(skc[e], Wp[e*64], a);
    g_kcbase[((size_t)k*CC + c)*64 + j] = a;
}

// ---------------------------------------------------------------------------
// f1: m_next. 256-row tiles, 512 threads, 8 rows (row-pair packed) x 4 cols.
// (unchanged from R5)
// ---------------------------------------------------------------------------
__device__ __forceinline__ void gemm64_rp(ull acc[4][4], const float* W, const float* Xt, int rbase)
{
    #pragma unroll 8
    for (int kk = 0; kk < 64; kk++) {
        float4 w4 = *(const float4*)(W + kk*64);
        ull wd0=dup2(w4.x), wd1=dup2(w4.y), wd2=dup2(w4.z), wd3=dup2(w4.w);
        ulonglong2 ua = *(const ulonglong2*)(Xt + kk*RP1 + rbase);
        ulonglong2 ub = *(const ulonglong2*)(Xt + kk*RP1 + rbase + 4);
        fma2(acc[0][0],ua.x,wd0); fma2(acc[0][1],ua.x,wd1); fma2(acc[0][2],ua.x,wd2); fma2(acc[0][3],ua.x,wd3);
        fma2(acc[1][0],ua.y,wd0); fma2(acc[1][1],ua.y,wd1); fma2(acc[1][2],ua.y,wd2); fma2(acc[1][3],ua.y,wd3);
        fma2(acc[2][0],ub.x,wd0); fma2(acc[2][1],ub.x,wd1); fma2(acc[2][2],ub.x,wd2); fma2(acc[2][3],ub.x,wd3);
        fma2(acc[3][0],ub.y,wd0); fma2(acc[3][1],ub.y,wd1); fma2(acc[3][2],ub.y,wd2); fma2(acc[3][3],ub.y,wd3);
    }
}

__global__ void __launch_bounds__(512) f1_kernel(
    const int*   __restrict__ qt,  const float* __restrict__ ht,
    const float* __restrict__ oh,  const float* __restrict__ kc,
    const float* __restrict__ nwp,
    const float* __restrict__ Ws1, const float* __restrict__ bs1,
    const float* __restrict__ Ws2, const float* __restrict__ bs2,
    const float* __restrict__ Wn1, const float* __restrict__ Wn2,
    const float* __restrict__ bn2)
{
    extern __shared__ float sm[];
    float* sWn1 = sm;             // 8192 (ht-part rows 128..191, both k)
    float* sWn2 = sWn1 + 8192;    // 8192
    float* sbn2 = sWn2 + 8192;    // 128
    float* U_T  = sbn2 + 128;     // 64*260 = 16640
    float* H1_T = U_T  + 16640;   // 16640
    float* rmask= H1_T + 16640;   // 256
    float* radj = rmask + 256;    // 512
    float* xr   = radj + 512;     // 128 (masked-row scratch)
    float* hb   = xr + 128;       // 64
    __shared__ int s_mcnt;
    __shared__ int s_mrows[256];

    int tid = threadIdx.x;
    for (int i = tid; i < 8192; i += 512) {
        int k = i >> 12, rc = i & 4095;
        sWn1[i] = Wn1[k*16384 + 8192 + rc];   // rows 128..191 (ht part)
        sWn2[i] = Wn2[i];
    }
    if (tid < 128) sbn2[tid] = bn2[tid];
    float w = clampf(nwp[0], 0.1f, 0.9f);
    __syncthreads();

    int wid = tid >> 5, lane = tid & 31;
    int tr = (wid & 7) * 4 + (lane >> 3);   // 32 row-groups (8 rows each)
    int tc = (wid >> 3) * 8 + (lane & 7);   // 16 col-groups (4 cols each)
    int rbase = tr * 8, cbase = tc * 4;

    for (int tile = blockIdx.x; tile < NROWS/256; tile += gridDim.x) {
        int row0 = tile << 8;
        int c0 = row0 & 1023;
        if (tid == 0) s_mcnt = 0;
        __syncthreads();

        // U_T = clip(ht)^T  (float4 coalesced LDG, scalar transposed STS)
        for (int i = tid; i < 256*16; i += 512) {
            int r = i >> 4, q = i & 15;
            float4 v = *(const float4*)(ht + (size_t)(row0+r)*64 + q*4);
            U_T[(q*4+0)*RP1 + r] = clampf(v.x, -5.f, 5.f);
            U_T[(q*4+1)*RP1 + r] = clampf(v.y, -5.f, 5.f);
            U_T[(q*4+2)*RP1 + r] = clampf(v.z, -5.f, 5.f);
            U_T[(q*4+3)*RP1 + r] = clampf(v.w, -5.f, 5.f);
        }
        if (tid < 256) {
            int gid = row0 + tid; int b = gid >> 10; int c = gid & 1023;
            float m = oh[(size_t)qt[b]*CC + c];
            rmask[tid] = m;
            radj[tid]       = g_adj[c];
            radj[256 + tid] = g_adj[CC + c];
            if (m > 0.5f) { int p = atomicAdd(&s_mcnt, 1); s_mrows[p] = tid; }
        }
        __syncthreads();

        float nf[8][4];
        #pragma unroll
        for (int k = 0; k < 2; k++) {
            // Stage A: H1 = relu(kcbase + clip(ht) @ Wn1_ht[k])
            ull acc[4][4];
            const float* kcb = g_kcbase + ((size_t)k*CC + c0 + rbase)*64 + cbase;
            #pragma unroll
            for (int p = 0; p < 4; p++) {
                float4 a = *(const float4*)(kcb + (2*p)*64);
                float4 b = *(const float4*)(kcb + (2*p+1)*64);
                acc[p][0]=pk2(a.x,b.x); acc[p][1]=pk2(a.y,b.y);
                acc[p][2]=pk2(a.z,b.z); acc[p][3]=pk2(a.w,b.w);
            }
            gemm64_rp(acc, sWn1 + k*4096 + cbase, U_T, rbase);
            #pragma unroll
            for (int p = 0; p < 4; p++)
                #pragma unroll
                for (int c = 0; c < 4; c++) {
                    float2 v = up2(acc[p][c]);
                    v.x = fmaxf(v.x, 0.f); v.y = fmaxf(v.y, 0.f);
                    *(float2*)(H1_T + (cbase+c)*RP1 + rbase + 2*p) = v;
                }
            __syncthreads();

            // Stage B: nb = clamp(H1 @ Wn2[k] + bn2[k], 0, 5); fold into nf
            #pragma unroll
            for (int c = 0; c < 4; c++) {
                ull b = dup2(sbn2[k*64 + cbase + c]);
                acc[0][c]=b; acc[1][c]=b; acc[2][c]=b; acc[3][c]=b;
            }
            gemm64_rp(acc, sWn2 + k*4096 + cbase, H1_T, rbase);
            #pragma unroll
            for (int p = 0; p < 4; p++) {
                float a0 = radj[k*256 + rbase + 2*p];
                float a1 = radj[k*256 + rbase + 2*p + 1];
                #pragma unroll
                for (int c = 0; c < 4; c++) {
                    float2 v = up2(acc[p][c]);
                    float v0 = a0 * clampf(v.x, 0.f, 5.f);
                    float v1 = a1 * clampf(v.y, 0.f, 5.f);
                    if (k == 0) {
                        nf[2*p][c]   = clampf(v0, -5.f, 5.f);
                        nf[2*p+1][c] = clampf(v1, -5.f, 5.f);
                    } else {
                        nf[2*p][c]   = clampf(w*nf[2*p][c]   + (1.f-w)*v0, -5.f, 5.f);
                        nf[2*p+1][c] = clampf(w*nf[2*p+1][c] + (1.f-w)*v1, -5.f, 5.f);
                    }
                }
            }
            __syncthreads();   // H1_T free for next k
        }

        // m_next for unmasked rows
        #pragma unroll
        for (int i = 0; i < 8; i++) {
            int r = rbase + i;
            if (rmask[r] <= 0.5f) {
                *(float4*)(&g_mnext[(size_t)(row0 + r)*64 + cbase]) =
                    make_float4(nf[i][0], nf[i][1], nf[i][2], nf[i][3]);
            }
        }

        // Rare masked rows: self MLP on RAW [ht, kc] (self_feat in [0,10])
        int mcnt = s_mcnt;
        for (int mi = 0; mi < mcnt; mi++) {
            int r = s_mrows[mi]; int gid = row0 + r; int c = gid & 1023;
            if (tid < 128)
                xr[tid] = (tid < 64) ? ht[(size_t)gid*64 + tid] : kc[c*64 + tid - 64];
            __syncthreads();
            if (tid < 64) {
                float a = bs1[tid];
                for (int j = 0; j < 128; j++) a = fmaf(xr[j], Ws1[j*64 + tid], a);
                hb[tid] = fmaxf(a, 0.f);
            }
            __syncthreads();
            if (tid < 64) {
                float a = bs2[tid];
                for (int j = 0; j < 64; j++) a = fmaf(hb[j], Ws2[j*64 + tid], a);
                g_mnext[(size_t)gid*64 + tid] = clampf(a, 0.f, 10.f);
            }
            __syncthreads();
        }
        __syncthreads();
    }
}

// ---------------------------------------------------------------------------
// f2 (new): dup-X SMEM + fused B/C gate loop.
//  Xd[64][XDP]: m (then res) stored duplicated: Xd[j][2r]=Xd[j][2r+1]=x[r][j]
//  Ht[64][HTP]: ht transposed plain.
//  Weights in smem: sWe, sWa (4096 ea), sWih/sWhh full 192-wide (12288 ea).
//  Biases / Wp / ea_w / bp read via LDG (L2) per tile.
// ---------------------------------------------------------------------------
__global__ void __launch_bounds__(512) f2_kernel(
    const float* __restrict__ ht,  const float* __restrict__ ea_w,
    const float* __restrict__ We,  const float* __restrict__ be,
    const float* __restrict__ Wa,  const float* __restrict__ ba,
    const float* __restrict__ Wih, const float* __restrict__ bih,
    const float* __restrict__ Whh, const float* __restrict__ bhh,
    const float* __restrict__ Wp,  const float* __restrict__ bp,
    float* __restrict__ out)
{
    extern __shared__ float sm[];
    float* Xd   = sm;             // 64*260 = 16640
    float* Ht   = Xd  + 16640;    // 64*132 = 8448
    float* sWe  = Ht  + 8448;     // 4096
    float* sWa  = sWe + 4096;     // 4096
    float* sWih = sWa + 4096;     // 12288
    float* sWhh = sWih + 12288;   // 12288
    float* sred = sWhh + 12288;   // 256   (total 58112 floats = 232448 B)

    int tid = threadIdx.x;
    for (int i = tid; i < 4096; i += 512) { sWe[i] = We[i]; sWa[i] = Wa[i]; }
    for (int i = tid; i < 12288; i += 512) { sWih[i] = Wih[i]; sWhh[i] = Whh[i]; }
    float bpv = bp[0];
    __syncthreads();

    int wid = tid >> 5, lane = tid & 31;
    int cgh = wid >> 3;                       // col half (0/1)
    int tr = (wid & 7) * 4 + (lane >> 3);     // 32 row-groups (4 rows)
    int tc = cgh * 8 + (lane & 7);            // 16 col-groups (4 cols)
    int rbase = tr * 4, cbase = tc * 4;

    for (int tile = blockIdx.x; tile < NROWS/128; tile += gridDim.x) {
        int row0 = tile << 7;

        // Fill (r-major lanes -> conflict-free STS)
        for (int i = tid; i < 2048; i += 512) {
            int q = i >> 7, r = i & 127;
            float4 m4 = *(const float4*)(g_mnext + (size_t)(row0+r)*64 + q*4);
            float4 h4 = *(const float4*)(ht      + (size_t)(row0+r)*64 + q*4);
            *(ull*)(Xd + (q*4+0)*XDP + 2*r) = dup2(m4.x);
            *(ull*)(Xd + (q*4+1)*XDP + 2*r) = dup2(m4.y);
            *(ull*)(Xd + (q*4+2)*XDP + 2*r) = dup2(m4.z);
            *(ull*)(Xd + (q*4+3)*XDP + 2*r) = dup2(m4.w);
            Ht[(q*4+0)*HTP + r] = h4.x; Ht[(q*4+1)*HTP + r] = h4.y;
            Ht[(q*4+2)*HTP + r] = h4.z; Ht[(q*4+3)*HTP + r] = h4.w;
        }
        __syncthreads();

        // ---- Phase A: S = M@We+be, T = M@Wa+ba (dup-X, no MOVs) ----
        ull aS[4][2], aT[4][2];
        {
            float4 e4 = *(const float4*)(be + cbase);
            float4 a4 = *(const float4*)(ba + cbase);
            ull s0=pk2(e4.x,e4.y), s1=pk2(e4.z,e4.w);
            ull t0=pk2(a4.x,a4.y), t1=pk2(a4.z,a4.w);
            #pragma unroll
            for (int i = 0; i < 4; i++) { aS[i][0]=s0; aS[i][1]=s1; aT[i][0]=t0; aT[i][1]=t1; }
        }
        #pragma unroll 8
        for (int kk = 0; kk < 64; kk++) {
            ulonglong2 xa = *(const ulonglong2*)(Xd + kk*XDP + 2*rbase);
            ulonglong2 xb = *(const ulonglong2*)(Xd + kk*XDP + 2*rbase + 4);
            ulonglong2 wS = *(const ulonglong2*)(sWe + kk*64 + cbase);
            ulonglong2 wT = *(const ulonglong2*)(sWa + kk*64 + cbase);
            fma2(aS[0][0],xa.x,wS.x); fma2(aS[0][1],xa.x,wS.y); fma2(aT[0][0],xa.x,wT.x); fma2(aT[0][1],xa.x,wT.y);
            fma2(aS[1][0],xa.y,wS.x); fma2(aS[1][1],xa.y,wS.y); fma2(aT[1][0],xa.y,wT.x); fma2(aT[1][1],xa.y,wT.y);
            fma2(aS[2][0],xb.x,wS.x); fma2(aS[2][1],xb.x,wS.y); fma2(aT[2][0],xb.x,wT.x); fma2(aT[2][1],xb.x,wT.y);
            fma2(aS[3][0],xb.y,wS.x); fma2(aS[3][1],xb.y,wS.y); fma2(aT[3][0],xb.y,wT.x); fma2(aT[3][1],xb.y,wT.y);
        }

        // Read m for my cells (before overwrite), res = m - g*sig(S)*m + g*tanh(T)
        float resv[4][4];
        {
            float gi[4];
            #pragma unroll
            for (int i = 0; i < 4; i++) gi[i] = ea_w[(row0 + rbase + i) & 1023];
            #pragma unroll
            for (int i = 0; i < 4; i++) {
                #pragma unroll
                for (int q = 0; q < 2; q++) {
                    float2 s = up2(aS[i][q]);
                    float2 t = up2(aT[i][q]);
                    int c = cbase + 2*q;
                    float m0 = Xd[c*XDP + 2*(rbase+i)];
                    float m1 = Xd[(c+1)*XDP + 2*(rbase+i)];
                    resv[i][2*q]   = m0 - gi[i]*sigf(s.x)*m0 + gi[i]*tanhfast(t.x);
                    resv[i][2*q+1] = m1 - gi[i]*sigf(s.y)*m1 + gi[i]*tanhfast(t.y);
                }
            }
        }
        __syncthreads();     // all GEMM/m reads of Xd done
        #pragma unroll
        for (int c = 0; c < 4; c++) {
            *(float4*)(Xd + (cbase+c)*XDP + 2*rbase) =
                make_float4(resv[0][c], resv[0][c], resv[1][c], resv[1][c]);
            *(float4*)(Xd + (cbase+c)*XDP + 2*rbase + 4) =
                make_float4(resv[2][c], resv[2][c], resv[3][c], resv[3][c]);
        }
        __syncthreads();

        // ---- Phase BC: fused gates. res -> R,Z,I ; ht -> R,Z,H ----
        ull aR[4][2], aZ[4][2], aI[4][2], aH[4][2];
        {
            float4 bi = *(const float4*)(bih + cbase);
            float4 bh = *(const float4*)(bhh + cbase);
            float4 zi = *(const float4*)(bih + 64 + cbase);
            float4 zh = *(const float4*)(bhh + 64 + cbase);
            float4 ni = *(const float4*)(bih + 128 + cbase);
            float4 nh = *(const float4*)(bhh + 128 + cbase);
            ull r0=pk2(bi.x+bh.x, bi.y+bh.y), r1=pk2(bi.z+bh.z, bi.w+bh.w);
            ull z0=pk2(zi.x+zh.x, zi.y+zh.y), z1=pk2(zi.z+zh.z, zi.w+zh.w);
            ull i0=pk2(ni.x,ni.y), i1=pk2(ni.z,ni.w);
            ull h0=pk2(nh.x,nh.y), h1=pk2(nh.z,nh.w);
            #pragma unroll
            for (int i = 0; i < 4; i++) {
                aR[i][0]=r0; aR[i][1]=r1; aZ[i][0]=z0; aZ[i][1]=z1;
                aI[i][0]=i0; aI[i][1]=i1; aH[i][0]=h0; aH[i][1]=h1;
            }
        }
        #pragma unroll 4
        for (int kk = 0; kk < 64; kk++) {
            // res half: dup-X loads, 3 weight loads, 24 fma2
            {
                ulonglong2 xa = *(const ulonglong2*)(Xd + kk*XDP + 2*rbase);
                ulonglong2 xb = *(const ulonglong2*)(Xd + kk*XDP + 2*rbase + 4);
                ulonglong2 wr = *(const ulonglong2*)(sWih + kk*192 + cbase);
                ulonglong2 wz = *(const ulonglong2*)(sWih + kk*192 + 64 + cbase);
                ulonglong2 wi = *(const ulonglong2*)(sWih + kk*192 + 128 + cbase);
                fma2(aR[0][0],xa.x,wr.x); fma2(aR[0][1],xa.x,wr.y); fma2(aZ[0][0],xa.x,wz.x); fma2(aZ[0][1],xa.x,wz.y); fma2(aI[0][0],xa.x,wi.x); fma2(aI[0][1],xa.x,wi.y);
                fma2(aR[1][0],xa.y,wr.x); fma2(aR[1][1],xa.y,wr.y); fma2(aZ[1][0],xa.y,wz.x); fma2(aZ[1][1],xa.y,wz.y); fma2(aI[1][0],xa.y,wi.x); fma2(aI[1][1],xa.y,wi.y);
                fma2(aR[2][0],xb.x,wr.x); fma2(aR[2][1],xb.x,wr.y); fma2(aZ[2][0],xb.x,wz.x); fma2(aZ[2][1],xb.x,wz.y); fma2(aI[2][0],xb.x,wi.x); fma2(aI[2][1],xb.x,wi.y);
                fma2(aR[3][0],xb.y,wr.x); fma2(aR[3][1],xb.y,wr.y); fma2(aZ[3][0],xb.y,wz.x); fma2(aZ[3][1],xb.y,wz.y); fma2(aI[3][0],xb.y,wi.x); fma2(aI[3][1],xb.y,wi.y);
            }
            // ht half: plain load + dups, 3 weight loads, 24 fma2
            {
                float4 h4 = *(const float4*)(Ht + kk*HTP + rbase);
                ull h0=dup2(h4.x), h1=dup2(h4.y), h2=dup2(h4.z), h3=dup2(h4.w);
                ulonglong2 wr = *(const ulonglong2*)(sWhh + kk*192 + cbase);
                ulonglong2 wz = *(const ulonglong2*)(sWhh + kk*192 + 64 + cbase);
                ulonglong2 wh = *(const ulonglong2*)(sWhh + kk*192 + 128 + cbase);
                fma2(aR[0][0],h0,wr.x); fma2(aR[0][1],h0,wr.y); fma2(aZ[0][0],h0,wz.x); fma2(aZ[0][1],h0,wz.y); fma2(aH[0][0],h0,wh.x); fma2(aH[0][1],h0,wh.y);
                fma2(aR[1][0],h1,wr.x); fma2(aR[1][1],h1,wr.y); fma2(aZ[1][0],h1,wz.x); fma2(aZ[1][1],h1,wz.y); fma2(aH[1][0],h1,wh.x); fma2(aH[1][1],h1,wh.y);
                fma2(aR[2][0],h2,wr.x); fma2(aR[2][1],h2,wr.y); fma2(aZ[2][0],h2,wz.x); fma2(aZ[2][1],h2,wz.y); fma2(aH[2][0],h2,wh.x); fma2(aH[2][1],h2,wh.y);
                fma2(aR[3][0],h3,wr.x); fma2(aR[3][1],h3,wr.y); fma2(aZ[3][0],h3,wz.x); fma2(aZ[3][1],h3,wz.y); fma2(aH[3][0],h3,wh.x); fma2(aH[3][1],h3,wh.y);
            }
        }

        // ---- Epilogue: gates, h_next, head ----
        float wp4v[4];
        { float4 wp4 = *(const float4*)(Wp + cbase);
          wp4v[0]=wp4.x; wp4v[1]=wp4.y; wp4v[2]=wp4.z; wp4v[3]=wp4.w; }
        #pragma unroll
        for (int i = 0; i < 4; i++) {
            int r = rbase + i;
            float py = 0.f;
            #pragma unroll
            for (int q = 0; q < 2; q++) {
                float2 vr = up2(aR[i][q]);
                float2 vz = up2(aZ[i][q]);
                float2 vi = up2(aI[i][q]);
                float2 vh = up2(aH[i][q]);
                int c = cbase + 2*q;
                float rg0 = sigf(vr.x), rg1 = sigf(vr.y);
                float zg0 = sigf(vz.x), zg1 = sigf(vz.y);
                float n0 = tanhfast(vi.x + rg0*vh.x);
                float n1 = tanhfast(vi.y + rg1*vh.y);
                float h0 = Ht[c*HTP + r];
                float h1 = Ht[(c+1)*HTP + r];
                float hn0 = (1.f - zg0)*n0 + zg0*h0;
                float hn1 = (1.f - zg1)*n1 + zg1*h1;
                py = fmaf(hn0, wp4v[2*q],   py);
                py = fmaf(hn1, wp4v[2*q+1], py);
            }
            // reduce over this warp's 8 col-groups (lanes sharing lane>>3)
            py += __shfl_xor_sync(0xffffffffu, py, 1, 8);
            py += __shfl_xor_sync(0xffffffffu, py, 2, 8);
            py += __shfl_xor_sync(0xffffffffu, py, 4, 8);
            if ((lane & 7) == 0) sred[cgh*128 + r] = py;
        }
        __syncthreads();
        if (tid < 128)
            out[row0 + tid] = sigf(sred[tid] + sred[128 + tid] + bpv);
        __syncthreads();
    }
}

// ---------------------------------------------------------------------------
extern "C" void kernel_launch(void* const* d_in, const int* in_sizes, int n_in,
                              void* d_out, int out_size)
{
    const int*   qt  = (const int*)  d_in[1];
    const float* ht  = (const float*)d_in[2];
    const float* oh  = (const float*)d_in[3];
    const float* kc  = (const float*)d_in[4];
    const float* gr  = (const float*)d_in[5];
    const float* nw  = (const float*)d_in[6];
    const float* Ws1 = (const float*)d_in[7];
    const float* bs1 = (const float*)d_in[8];
    const float* Ws2 = (const float*)d_in[9];
    const float* bs2 = (const float*)d_in[10];
    const float* Wn1 = (const float*)d_in[11];
    const float* bn1 = (const float*)d_in[12];
    const float* Wn2 = (const float*)d_in[13];
    const float* bn2 = (const float*)d_in[14];
    const float* ea  = (const float*)d_in[15];
    const float* We  = (const float*)d_in[16];
    const float* be  = (const float*)d_in[17];
    const float* Wa  = (const float*)d_in[18];
    const float* ba  = (const float*)d_in[19];
    const float* Wih = (const float*)d_in[20];
    const float* bih = (const float*)d_in[21];
    const float* Whh = (const float*)d_in[22];
    const float* bhh = (const float*)d_in[23];
    const float* Wp  = (const float*)d_in[24];
    const float* bp  = (const float*)d_in[25];
    float* out = (float*)d_out;

    int smc = 148;
    if (cudaDeviceGetAttribute(&smc, cudaDevAttrMultiProcessorCount, 0) != cudaSuccess || smc <= 0)
        smc = 148;

    size_t smem1 = (size_t)(8192+8192+128+16640+16640+256+512+128+64) * 4;   // ~203 KB
    size_t smem2 = (size_t)(16640+8448+4096+4096+12288+12288+256) * 4;       // 232448 B (max)
    cudaFuncSetAttribute(f1_kernel, cudaFuncAttributeMaxDynamicSharedMemorySize, (int)smem1);
    cudaFuncSetAttribute(f2_kernel, cudaFuncAttributeMaxDynamicSharedMemorySize, (int)smem2);

    adj_kernel<<<1, 1024>>>(qt, oh, gr);
    kcbase_kernel<<<1024, 128>>>(kc, Wn1, bn1);
    f1_kernel<<<smc, 512, smem1>>>(qt, ht, oh, kc, nw, Ws1, bs1, Ws2, bs2, Wn1, Wn2, bn2);
    f2_kernel<<<smc, 512, smem2>>>(ht, ea, We, be, Wa, ba, Wih, bih, Whh, bhh, Wp, bp, out);
}

// round 7
// speedup vs baseline: 1.6546x; 1.6546x over previous
#include <cuda_runtime.h>
#include <cstdint>
#include <math.h>

#define CC 1024
#define NROWS (256*1024)
#define RP1 260     // f1 transposed row pad
#define XP  68      // f2 row-major pad (bank-spread for fragment gathers)

typedef unsigned long long ull;

// Scratch (allocation-free rule: __device__ globals)
__device__ float g_adj[2*CC];
__device__ float g_kcbase[2*CC*64];
__device__ float g_mnext[(size_t)NROWS * 64];

// ---- packed f32x2 helpers (f1) --------------------------------------------
__device__ __forceinline__ ull dup2(float x){ ull r; asm("mov.b64 %0,{%1,%1};":"=l"(r):"f"(x)); return r; }
__device__ __forceinline__ ull pk2(float lo, float hi){ ull r; asm("mov.b64 %0,{%1,%2};":"=l"(r):"f"(lo),"f"(hi)); return r; }
__device__ __forceinline__ float2 up2(ull v){ float2 f; asm("mov.b64 {%0,%1},%2;":"=f"(f.x),"=f"(f.y):"l"(v)); return f; }
__device__ __forceinline__ void fma2(ull&d, ull a, ull b){ asm("fma.rn.f32x2 %0,%1,%2,%0;":"+l"(d):"l"(a),"l"(b)); }

__device__ __forceinline__ float clampf(float v,float lo,float hi){ return fminf(fmaxf(v,lo),hi); }
__device__ __forceinline__ float sigf(float x){ return __fdividef(1.f, 1.f + __expf(-x)); }
__device__ __forceinline__ float tanhfast(float x){
    float t = __expf(-2.f*fabsf(x));
    float r = __fdividef(1.f - t, 1.f + t);
    return copysignf(r, x);
}

// ---- tf32 mma helpers (f2) -------------------------------------------------
__device__ __forceinline__ unsigned tf32r(float f){
    unsigned u; asm("cvt.rna.tf32.f32 %0, %1;" : "=r"(u) : "f"(f)); return u;
}
__device__ __forceinline__ void mma8(float c[4], const unsigned a[4], unsigned b0, unsigned b1){
    asm volatile(
        "mma.sync.aligned.m16n8k8.row.col.f32.tf32.tf32.f32 "
        "{%0,%1,%2,%3},{%4,%5,%6,%7},{%8,%9},{%0,%1,%2,%3};"
        : "+f"(c[0]),"+f"(c[1]),"+f"(c[2]),"+f"(c[3])
        : "r"(a[0]),"r"(a[1]),"r"(a[2]),"r"(a[3]),"r"(b0),"r"(b1));
}
// A fragment (16x8, row-major) from raw fp32 smem, rounded to tf32.
__device__ __forceinline__ void ldfragA(unsigned a[4], const float* X, int rowbase, int ks, int t, int g){
    const float* p0 = X + (rowbase + g)*XP + ks*8;
    const float* p1 = p0 + 8*XP;
    a[0]=tf32r(p0[t]); a[1]=tf32r(p1[t]); a[2]=tf32r(p0[t+4]); a[3]=tf32r(p1[t+4]);
}

// ---------------------------------------------------------------------------
// adj: mask0 has ~5 nonzeros -> compact + gather
// ---------------------------------------------------------------------------
__global__ void adj_kernel(const int* __restrict__ qt,
                           const float* __restrict__ oh,
                           const float* __restrict__ graphs)
{
    __shared__ int   s_idx[CC];
    __shared__ float s_val[CC];
    __shared__ int   s_cnt;
    __shared__ float s_sum;

    int t = threadIdx.x;
    if (t == 0) { s_cnt = 0; s_sum = 0.f; }
    __syncthreads();

    int q0 = qt[0];
    float m = oh[(size_t)q0 * CC + t];
    if (m != 0.f) {
        int p = atomicAdd(&s_cnt, 1);
        s_idx[p] = t; s_val[p] = m;
        atomicAdd(&s_sum, m);
    }
    __syncthreads();

    float denom = fmaxf(s_sum, 1.f);
    int nnz = s_cnt;
    for (int k = 0; k < 2; k++) {
        float acc = 0.f;
        for (int i = 0; i < nnz; i++)
            acc += s_val[i] * graphs[(size_t)k*CC*CC + (size_t)s_idx[i]*CC + t];
        g_adj[k*CC + t] = clampf(acc / denom, -5.f, 5.f);
    }
}

// ---------------------------------------------------------------------------
// kcbase[k][c][j] = bn1[k][j] + sum_e clip(kc[c][e],±5) * Wn1[k][192+e][j]
// ---------------------------------------------------------------------------
__global__ void kcbase_kernel(const float* __restrict__ kc,
                              const float* __restrict__ Wn1,
                              const float* __restrict__ bn1)
{
    __shared__ float skc[64];
    int c = blockIdx.x;
    int tid = threadIdx.x;              // 128
    if (tid < 64) skc[tid] = clampf(kc[c*64 + tid], -5.f, 5.f);
    __syncthreads();
    int k = tid >> 6, j = tid & 63;
    float a = bn1[k*64 + j];
    const float* Wp = Wn1 + k*16384 + 12288 + j;
    #pragma unroll 8
    for (int e = 0; e < 64; e++) a = fmaf(skc[e], Wp[e*64], a);
    g_kcbase[((size_t)k*CC + c)*64 + j] = a;
}

// ---------------------------------------------------------------------------
// f1 (scalar FFMA2 path, unchanged from R5)
// ---------------------------------------------------------------------------
__device__ __forceinline__ void gemm64_rp(ull acc[4][4], const float* W, const float* Xt, int rbase)
{
    #pragma unroll 8
    for (int kk = 0; kk < 64; kk++) {
        float4 w4 = *(const float4*)(W + kk*64);
        ull wd0=dup2(w4.x), wd1=dup2(w4.y), wd2=dup2(w4.z), wd3=dup2(w4.w);
        ulonglong2 ua = *(const ulonglong2*)(Xt + kk*RP1 + rbase);
        ulonglong2 ub = *(const ulonglong2*)(Xt + kk*RP1 + rbase + 4);
        fma2(acc[0][0],ua.x,wd0); fma2(acc[0][1],ua.x,wd1); fma2(acc[0][2],ua.x,wd2); fma2(acc[0][3],ua.x,wd3);
        fma2(acc[1][0],ua.y,wd0); fma2(acc[1][1],ua.y,wd1); fma2(acc[1][2],ua.y,wd2); fma2(acc[1][3],ua.y,wd3);
        fma2(acc[2][0],ub.x,wd0); fma2(acc[2][1],ub.x,wd1); fma2(acc[2][2],ub.x,wd2); fma2(acc[2][3],ub.x,wd3);
        fma2(acc[3][0],ub.y,wd0); fma2(acc[3][1],ub.y,wd1); fma2(acc[3][2],ub.y,wd2); fma2(acc[3][3],ub.y,wd3);
    }
}

__global__ void __launch_bounds__(512) f1_kernel(
    const int*   __restrict__ qt,  const float* __restrict__ ht,
    const float* __restrict__ oh,  const float* __restrict__ kc,
    const float* __restrict__ nwp,
    const float* __restrict__ Ws1, const float* __restrict__ bs1,
    const float* __restrict__ Ws2, const float* __restrict__ bs2,
    const float* __restrict__ Wn1, const float* __restrict__ Wn2,
    const float* __restrict__ bn2)
{
    extern __shared__ float sm[];
    float* sWn1 = sm;             // 8192
    float* sWn2 = sWn1 + 8192;    // 8192
    float* sbn2 = sWn2 + 8192;    // 128
    float* U_T  = sbn2 + 128;     // 16640
    float* H1_T = U_T  + 16640;   // 16640
    float* rmask= H1_T + 16640;   // 256
    float* radj = rmask + 256;    // 512
    float* xr   = radj + 512;     // 128
    float* hb   = xr + 128;       // 64
    __shared__ int s_mcnt;
    __shared__ int s_mrows[256];

    int tid = threadIdx.x;
    for (int i = tid; i < 8192; i += 512) {
        int k = i >> 12, rc = i & 4095;
        sWn1[i] = Wn1[k*16384 + 8192 + rc];
        sWn2[i] = Wn2[i];
    }
    if (tid < 128) sbn2[tid] = bn2[tid];
    float w = clampf(nwp[0], 0.1f, 0.9f);
    __syncthreads();

    int wid = tid >> 5, lane = tid & 31;
    int tr = (wid & 7) * 4 + (lane >> 3);
    int tc = (wid >> 3) * 8 + (lane & 7);
    int rbase = tr * 8, cbase = tc * 4;

    for (int tile = blockIdx.x; tile < NROWS/256; tile += gridDim.x) {
        int row0 = tile << 8;
        int c0 = row0 & 1023;
        if (tid == 0) s_mcnt = 0;
        __syncthreads();

        for (int i = tid; i < 256*16; i += 512) {
            int r = i >> 4, q = i & 15;
            float4 v = *(const float4*)(ht + (size_t)(row0+r)*64 + q*4);
            U_T[(q*4+0)*RP1 + r] = clampf(v.x, -5.f, 5.f);
            U_T[(q*4+1)*RP1 + r] = clampf(v.y, -5.f, 5.f);
            U_T[(q*4+2)*RP1 + r] = clampf(v.z, -5.f, 5.f);
            U_T[(q*4+3)*RP1 + r] = clampf(v.w, -5.f, 5.f);
        }
        if (tid < 256) {
            int gid = row0 + tid; int b = gid >> 10; int c = gid & 1023;
            float m = oh[(size_t)qt[b]*CC + c];
            rmask[tid] = m;
            radj[tid]       = g_adj[c];
            radj[256 + tid] = g_adj[CC + c];
            if (m > 0.5f) { int p = atomicAdd(&s_mcnt, 1); s_mrows[p] = tid; }
        }
        __syncthreads();

        float nf[8][4];
        #pragma unroll
        for (int k = 0; k < 2; k++) {
            ull acc[4][4];
            const float* kcb = g_kcbase + ((size_t)k*CC + c0 + rbase)*64 + cbase;
            #pragma unroll
            for (int p = 0; p < 4; p++) {
                float4 a = *(const float4*)(kcb + (2*p)*64);
                float4 b = *(const float4*)(kcb + (2*p+1)*64);
                acc[p][0]=pk2(a.x,b.x); acc[p][1]=pk2(a.y,b.y);
                acc[p][2]=pk2(a.z,b.z); acc[p][3]=pk2(a.w,b.w);
            }
            gemm64_rp(acc, sWn1 + k*4096 + cbase, U_T, rbase);
            #pragma unroll
            for (int p = 0; p < 4; p++)
                #pragma unroll
                for (int c = 0; c < 4; c++) {
                    float2 v = up2(acc[p][c]);
                    v.x = fmaxf(v.x, 0.f); v.y = fmaxf(v.y, 0.f);
                    *(float2*)(H1_T + (cbase+c)*RP1 + rbase + 2*p) = v;
                }
            __syncthreads();

            #pragma unroll
            for (int c = 0; c < 4; c++) {
                ull b = dup2(sbn2[k*64 + cbase + c]);
                acc[0][c]=b; acc[1][c]=b; acc[2][c]=b; acc[3][c]=b;
            }
            gemm64_rp(acc, sWn2 + k*4096 + cbase, H1_T, rbase);
            #pragma unroll
            for (int p = 0; p < 4; p++) {
                float a0 = radj[k*256 + rbase + 2*p];
                float a1 = radj[k*256 + rbase + 2*p + 1];
                #pragma unroll
                for (int c = 0; c < 4; c++) {
                    float2 v = up2(acc[p][c]);
                    float v0 = a0 * clampf(v.x, 0.f, 5.f);
                    float v1 = a1 * clampf(v.y, 0.f, 5.f);
                    if (k == 0) {
                        nf[2*p][c]   = clampf(v0, -5.f, 5.f);
                        nf[2*p+1][c] = clampf(v1, -5.f, 5.f);
                    } else {
                        nf[2*p][c]   = clampf(w*nf[2*p][c]   + (1.f-w)*v0, -5.f, 5.f);
                        nf[2*p+1][c] = clampf(w*nf[2*p+1][c] + (1.f-w)*v1, -5.f, 5.f);
                    }
                }
            }
            __syncthreads();
        }

        #pragma unroll
        for (int i = 0; i < 8; i++) {
            int r = rbase + i;
            if (rmask[r] <= 0.5f) {
                *(float4*)(&g_mnext[(size_t)(row0 + r)*64 + cbase]) =
                    make_float4(nf[i][0], nf[i][1], nf[i][2], nf[i][3]);
            }
        }

        int mcnt = s_mcnt;
        for (int mi = 0; mi < mcnt; mi++) {
            int r = s_mrows[mi]; int gid = row0 + r; int c = gid & 1023;
            if (tid < 128)
                xr[tid] = (tid < 64) ? ht[(size_t)gid*64 + tid] : kc[c*64 + tid - 64];
            __syncthreads();
            if (tid < 64) {
                float a = bs1[tid];
                for (int j = 0; j < 128; j++) a = fmaf(xr[j], Ws1[j*64 + tid], a);
                hb[tid] = fmaxf(a, 0.f);
            }
            __syncthreads();
            if (tid < 64) {
                float a = bs2[tid];
                for (int j = 0; j < 64; j++) a = fmaf(hb[j], Ws2[j*64 + tid], a);
                g_mnext[(size_t)gid*64 + tid] = clampf(a, 0.f, 10.f);
            }
            __syncthreads();
        }
        __syncthreads();
    }
}

// ---------------------------------------------------------------------------
// f2 (tensor-core tf32): 128-row tiles, 512 threads.
// 16 warps = 4 row-groups (32 rows) x 4 col-groups (16 cols).
// m16n8k8 tf32 mma; weights pre-packed into fragment order once per block.
// ---------------------------------------------------------------------------
__global__ void __launch_bounds__(512) f2_kernel(
    const float* __restrict__ ht,  const float* __restrict__ ea_w,
    const float* __restrict__ We,  const float* __restrict__ be,
    const float* __restrict__ Wa,  const float* __restrict__ ba,
    const float* __restrict__ Wih, const float* __restrict__ bih,
    const float* __restrict__ Whh, const float* __restrict__ bhh,
    const float* __restrict__ Wp,  const float* __restrict__ bp,
    float* __restrict__ out)
{
    extern __shared__ float sm[];
    float*  Xs   = sm;                       // 128*68 = 8704 (m, then res, raw fp32)
    float*  Hs   = Xs + 8704;                // 8704 (ht raw fp32)
    float2* PWe  = (float2*)(Hs + 8704);     // [8ks][8nt][32] = 2048 f2 (4096 f)
    float2* PWa  = PWe + 2048;               // 4096 f
    float2* PWih = PWa + 2048;               // [8ks][24nt][32] = 6144 f2 (12288 f)
    float2* PWhh = PWih + 6144;              // 12288 f
    float*  sbe  = (float*)(PWhh + 6144);    // 64
    float*  sba  = sbe + 64;                 // 64
    float*  sbrz = sba + 64;                 // 128 (bih+bhh for r|z)
    float*  sbI  = sbrz + 128;               // 64
    float*  sbH  = sbI + 64;                 // 64
    float*  sWp  = sbH + 64;                 // 64
    float*  sred = sWp + 64;                 // 512
    // total = 51136 floats = 204544 B

    int tid = threadIdx.x;

    // ---- one-time weight packing into mma B-fragment order (tf32-rounded) ----
    for (int i = tid; i < 2048; i += 512) {
        int lane = i & 31, nt = (i >> 5) & 7, ks = i >> 8;
        int t = lane & 3, g = lane >> 2;
        int r0 = ks*8 + t, r1 = r0 + 4, c = nt*8 + g;
        float2 v;
        v.x = __uint_as_float(tf32r(We[r0*64 + c]));
        v.y = __uint_as_float(tf32r(We[r1*64 + c]));
        PWe[i] = v;
        v.x = __uint_as_float(tf32r(Wa[r0*64 + c]));
        v.y = __uint_as_float(tf32r(Wa[r1*64 + c]));
        PWa[i] = v;
    }
    for (int i = tid; i < 6144; i += 512) {
        int lane = i & 31; int rest = i >> 5; int nt = rest % 24, ks = rest / 24;
        int t = lane & 3, g = lane >> 2;
        int r0 = ks*8 + t, r1 = r0 + 4, c = nt*8 + g;
        float2 v;
        v.x = __uint_as_float(tf32r(Wih[r0*192 + c]));
        v.y = __uint_as_float(tf32r(Wih[r1*192 + c]));
        PWih[i] = v;
        v.x = __uint_as_float(tf32r(Whh[r0*192 + c]));
        v.y = __uint_as_float(tf32r(Whh[r1*192 + c]));
        PWhh[i] = v;
    }
    if (tid < 64) {
        sbe[tid] = be[tid]; sba[tid] = ba[tid]; sWp[tid] = Wp[tid];
        sbI[tid] = bih[128 + tid]; sbH[tid] = bhh[128 + tid];
    }
    if (tid < 128) sbrz[tid] = bih[tid] + bhh[tid];
    float bpv = bp[0];
    __syncthreads();

    int wid = tid >> 5, lane = tid & 31;
    int rg = wid & 3, cg = wid >> 2;
    int t = lane & 3, g = lane >> 2;
    int rb = rg * 32, cb = cg * 16;

    for (int tile = blockIdx.x; tile < NROWS/128; tile += gridDim.x) {
        int row0 = tile << 7;

        // fill Xs (m) and Hs (ht), row-major raw fp32
        for (int i = tid; i < 2048; i += 512) {
            int r = i >> 4, q = i & 15;
            float4 m4 = *(const float4*)(g_mnext + (size_t)(row0+r)*64 + q*4);
            float4 h4 = *(const float4*)(ht      + (size_t)(row0+r)*64 + q*4);
            *(float4*)(Xs + r*XP + q*4) = m4;
            *(float4*)(Hs + r*XP + q*4) = h4;
        }
        __syncthreads();

        // ---- Phase A: S = m@We+be, T = m@Wa+ba ----
        float S[2][2][4], T[2][2][4];
        #pragma unroll
        for (int mt = 0; mt < 2; mt++)
            #pragma unroll
            for (int nt = 0; nt < 2; nt++) {
                int c = cb + nt*8 + 2*t;
                S[mt][nt][0]=sbe[c]; S[mt][nt][1]=sbe[c+1]; S[mt][nt][2]=sbe[c]; S[mt][nt][3]=sbe[c+1];
                T[mt][nt][0]=sba[c]; T[mt][nt][1]=sba[c+1]; T[mt][nt][2]=sba[c]; T[mt][nt][3]=sba[c+1];
            }
        #pragma unroll
        for (int ks = 0; ks < 8; ks++) {
            unsigned f0[4], f1[4];
            ldfragA(f0, Xs, rb,      ks, t, g);
            ldfragA(f1, Xs, rb + 16, ks, t, g);
            #pragma unroll
            for (int nt = 0; nt < 2; nt++) {
                int bi = (ks*8 + cg*2 + nt)*32 + lane;
                float2 bw = PWe[bi];
                unsigned b0 = __float_as_uint(bw.x), b1 = __float_as_uint(bw.y);
                mma8(S[0][nt], f0, b0, b1); mma8(S[1][nt], f1, b0, b1);
                bw = PWa[bi];
                b0 = __float_as_uint(bw.x); b1 = __float_as_uint(bw.y);
                mma8(T[0][nt], f0, b0, b1); mma8(T[1][nt], f1, b0, b1);
            }
        }

        // res = m - g*sig(S)*m + g*tanh(T) (raw m from smem)
        float resv[2][2][4];
        float ga[4];
        #pragma unroll
        for (int q = 0; q < 4; q++)
            ga[q] = ea_w[(row0 + rb + (q>>1)*16 + (q&1)*8 + g) & 1023];
        #pragma unroll
        for (int mt = 0; mt < 2; mt++)
            #pragma unroll
            for (int nt = 0; nt < 2; nt++) {
                int c = cb + nt*8 + 2*t;
                int rA = rb + mt*16 + g;
                float2 m0 = *(const float2*)(Xs + rA*XP + c);
                float2 m1 = *(const float2*)(Xs + (rA+8)*XP + c);
                float g0 = ga[2*mt], g1 = ga[2*mt+1];
                resv[mt][nt][0] = m0.x - g0*sigf(S[mt][nt][0])*m0.x + g0*tanhfast(T[mt][nt][0]);
                resv[mt][nt][1] = m0.y - g0*sigf(S[mt][nt][1])*m0.y + g0*tanhfast(T[mt][nt][1]);
                resv[mt][nt][2] = m1.x - g1*sigf(S[mt][nt][2])*m1.x + g1*tanhfast(T[mt][nt][2]);
                resv[mt][nt][3] = m1.y - g1*sigf(S[mt][nt][3])*m1.y + g1*tanhfast(T[mt][nt][3]);
            }
        __syncthreads();
        #pragma unroll
        for (int mt = 0; mt < 2; mt++)
            #pragma unroll
            for (int nt = 0; nt < 2; nt++) {
                int c = cb + nt*8 + 2*t;
                int rA = rb + mt*16 + g;
                *(float2*)(Xs + rA*XP + c)     = make_float2(resv[mt][nt][0], resv[mt][nt][1]);
                *(float2*)(Xs + (rA+8)*XP + c) = make_float2(resv[mt][nt][2], resv[mt][nt][3]);
            }
        __syncthreads();

        // ---- Phase BC: R,Z (res+ht), I (res), H (ht) ----
        float R[2][2][4], Z[2][2][4], I_[2][2][4], Hh[2][2][4];
        #pragma unroll
        for (int mt = 0; mt < 2; mt++)
            #pragma unroll
            for (int nt = 0; nt < 2; nt++) {
                int c = cb + nt*8 + 2*t;
                R[mt][nt][0]=sbrz[c];    R[mt][nt][1]=sbrz[c+1];    R[mt][nt][2]=sbrz[c];    R[mt][nt][3]=sbrz[c+1];
                Z[mt][nt][0]=sbrz[64+c]; Z[mt][nt][1]=sbrz[64+c+1]; Z[mt][nt][2]=sbrz[64+c]; Z[mt][nt][3]=sbrz[64+c+1];
                I_[mt][nt][0]=sbI[c];    I_[mt][nt][1]=sbI[c+1];    I_[mt][nt][2]=sbI[c];    I_[mt][nt][3]=sbI[c+1];
                Hh[mt][nt][0]=sbH[c];    Hh[mt][nt][1]=sbH[c+1];    Hh[mt][nt][2]=sbH[c];    Hh[mt][nt][3]=sbH[c+1];
            }
        #pragma unroll
        for (int ks = 0; ks < 8; ks++) {
            unsigned f0[4], f1[4];
            ldfragA(f0, Xs, rb,      ks, t, g);   // res
            ldfragA(f1, Xs, rb + 16, ks, t, g);
            #pragma unroll
            for (int nt = 0; nt < 2; nt++) {
                int bi = (ks*24 + cg*2 + nt)*32 + lane;
                float2 bw = PWih[bi];
                unsigned b0 = __float_as_uint(bw.x), b1 = __float_as_uint(bw.y);
                mma8(R[0][nt], f0, b0, b1); mma8(R[1][nt], f1, b0, b1);
                bw = PWih[bi + 256];
                b0 = __float_as_uint(bw.x); b1 = __float_as_uint(bw.y);
                mma8(Z[0][nt], f0, b0, b1); mma8(Z[1][nt], f1, b0, b1);
                bw = PWih[bi + 512];
                b0 = __float_as_uint(bw.x); b1 = __float_as_uint(bw.y);
                mma8(I_[0][nt], f0, b0, b1); mma8(I_[1][nt], f1, b0, b1);
            }
            ldfragA(f0, Hs, rb,      ks, t, g);   // ht
            ldfragA(f1, Hs, rb + 16, ks, t, g);
            #pragma unroll
            for (int nt = 0; nt < 2; nt++) {
                int bi = (ks*24 + cg*2 + nt)*32 + lane;
                float2 bw = PWhh[bi];
                unsigned b0 = __float_as_uint(bw.x), b1 = __float_as_uint(bw.y);
                mma8(R[0][nt], f0, b0, b1); mma8(R[1][nt], f1, b0, b1);
                bw = PWhh[bi + 256];
                b0 = __float_as_uint(bw.x); b1 = __float_as_uint(bw.y);
                mma8(Z[0][nt], f0, b0, b1); mma8(Z[1][nt], f1, b0, b1);
                bw = PWhh[bi + 512];
                b0 = __float_as_uint(bw.x); b1 = __float_as_uint(bw.y);
                mma8(Hh[0][nt], f0, b0, b1); mma8(Hh[1][nt], f1, b0, b1);
            }
        }

        // ---- epilogue: gates, h_next, head partial sums ----
        float py[4] = {0.f, 0.f, 0.f, 0.f};
        #pragma unroll
        for (int mt = 0; mt < 2; mt++)
            #pragma unroll
            for (int nt = 0; nt < 2; nt++) {
                int c = cb + nt*8 + 2*t;
                int rA = rb + mt*16 + g;
                float2 h0 = *(const float2*)(Hs + rA*XP + c);
                float2 h1 = *(const float2*)(Hs + (rA+8)*XP + c);
                float wc0 = sWp[c], wc1 = sWp[c+1];
                {
                    float rr = sigf(R[mt][nt][0]), zz = sigf(Z[mt][nt][0]);
                    float nn = tanhfast(I_[mt][nt][0] + rr*Hh[mt][nt][0]);
                    py[2*mt] = fmaf((1.f-zz)*nn + zz*h0.x, wc0, py[2*mt]);
                }
                {
                    float rr = sigf(R[mt][nt][1]), zz = sigf(Z[mt][nt][1]);
                    float nn = tanhfast(I_[mt][nt][1] + rr*Hh[mt][nt][1]);
                    py[2*mt] = fmaf((1.f-zz)*nn + zz*h0.y, wc1, py[2*mt]);
                }
                {
                    float rr = sigf(R[mt][nt][2]), zz = sigf(Z[mt][nt][2]);
                    float nn = tanhfast(I_[mt][nt][2] + rr*Hh[mt][nt][2]);
                    py[2*mt+1] = fmaf((1.f-zz)*nn + zz*h1.x, wc0, py[2*mt+1]);
                }
                {
                    float rr = sigf(R[mt][nt][3]), zz = sigf(Z[mt][nt][3]);
                    float nn = tanhfast(I_[mt][nt][3] + rr*Hh[mt][nt][3]);
                    py[2*mt+1] = fmaf((1.f-zz)*nn + zz*h1.y, wc1, py[2*mt+1]);
                }
            }
        #pragma unroll
        for (int q = 0; q < 4; q++) {
            py[q] += __shfl_xor_sync(0xffffffffu, py[q], 1, 4);
            py[q] += __shfl_xor_sync(0xffffffffu, py[q], 2, 4);
        }
        if (t == 0) {
            sred[cg*128 + rb + g]      = py[0];
            sred[cg*128 + rb + 8 + g]  = py[1];
            sred[cg*128 + rb + 16 + g] = py[2];
            sred[cg*128 + rb + 24 + g] = py[3];
        }
        __syncthreads();
        if (tid < 128)
            out[row0 + tid] = sigf(sred[tid] + sred[128+tid] + sred[256+tid] + sred[384+tid] + bpv);
        __syncthreads();
    }
}

// ---------------------------------------------------------------------------
extern "C" void kernel_launch(void* const* d_in, const int* in_sizes, int n_in,
                              void* d_out, int out_size)
{
    const int*   qt  = (const int*)  d_in[1];
    const float* ht  = (const float*)d_in[2];
    const float* oh  = (const float*)d_in[3];
    const float* kc  = (const float*)d_in[4];
    const float* gr  = (const float*)d_in[5];
    const float* nw  = (const float*)d_in[6];
    const float* Ws1 = (const float*)d_in[7];
    const float* bs1 = (const float*)d_in[8];
    const float* Ws2 = (const float*)d_in[9];
    const float* bs2 = (const float*)d_in[10];
    const float* Wn1 = (const float*)d_in[11];
    const float* bn1 = (const float*)d_in[12];
    const float* Wn2 = (const float*)d_in[13];
    const float* bn2 = (const float*)d_in[14];
    const float* ea  = (const float*)d_in[15];
    const float* We  = (const float*)d_in[16];
    const float* be  = (const float*)d_in[17];
    const float* Wa  = (const float*)d_in[18];
    const float* ba  = (const float*)d_in[19];
    const float* Wih = (const float*)d_in[20];
    const float* bih = (const float*)d_in[21];
    const float* Whh = (const float*)d_in[22];
    const float* bhh = (const float*)d_in[23];
    const float* Wp  = (const float*)d_in[24];
    const float* bp  = (const float*)d_in[25];
    float* out = (float*)d_out;

    int smc = 148;
    if (cudaDeviceGetAttribute(&smc, cudaDevAttrMultiProcessorCount, 0) != cudaSuccess || smc <= 0)
        smc = 148;

    size_t smem1 = (size_t)(8192+8192+128+16640+16640+256+512+128+64) * 4;   // ~203 KB
    size_t smem2 = (size_t)51136 * 4;                                        // 204544 B
    cudaFuncSetAttribute(f1_kernel, cudaFuncAttributeMaxDynamicSharedMemorySize, (int)smem1);
    cudaFuncSetAttribute(f2_kernel, cudaFuncAttributeMaxDynamicSharedMemorySize, (int)smem2);

    adj_kernel<<<1, 1024>>>(qt, oh, gr);
    kcbase_kernel<<<1024, 128>>>(kc, Wn1, bn1);
    f1_kernel<<<smc, 512, smem1>>>(qt, ht, oh, kc, nw, Ws1, bs1, Ws2, bs2, Wn1, Wn2, bn2);
    f2_kernel<<<smc, 512, smem2>>>(ht, ea, We, be, Wa, ba, Wih, bih, Whh, bhh, Wp, bp, out);
}

// round 8
// speedup vs baseline: 1.8443x; 1.1147x over previous
#include <cuda_runtime.h>
#include <cstdint>
#include <math.h>

#define CC 1024
#define NROWS (256*1024)
#define XP  68      // row-major pad (bank-spread for fragment gathers)

typedef unsigned long long ull;

// Scratch (allocation-free rule: __device__ globals)
__device__ float g_adj[2*CC];
__device__ float g_kcbase[2*CC*64];
__device__ float g_mnext[(size_t)NROWS * 64];

__device__ __forceinline__ float clampf(float v,float lo,float hi){ return fminf(fmaxf(v,lo),hi); }
__device__ __forceinline__ float sigf(float x){ return __fdividef(1.f, 1.f + __expf(-x)); }
__device__ __forceinline__ float tanhfast(float x){
    float t = __expf(-2.f*fabsf(x));
    float r = __fdividef(1.f - t, 1.f + t);
    return copysignf(r, x);
}

// ---- tf32 mma helpers -------------------------------------------------------
__device__ __forceinline__ unsigned tf32r(float f){
    unsigned u; asm("cvt.rna.tf32.f32 %0, %1;" : "=r"(u) : "f"(f)); return u;
}
__device__ __forceinline__ void mma8(float c[4], const unsigned a[4], unsigned b0, unsigned b1){
    asm volatile(
        "mma.sync.aligned.m16n8k8.row.col.f32.tf32.tf32.f32 "
        "{%0,%1,%2,%3},{%4,%5,%6,%7},{%8,%9},{%0,%1,%2,%3};"
        : "+f"(c[0]),"+f"(c[1]),"+f"(c[2]),"+f"(c[3])
        : "r"(a[0]),"r"(a[1]),"r"(a[2]),"r"(a[3]),"r"(b0),"r"(b1));
}
// A fragment (16x8, row-major) from raw fp32 smem, rounded to tf32.
__device__ __forceinline__ void ldfragA(unsigned a[4], const float* X, int rowbase, int ks, int t, int g){
    const float* p0 = X + (rowbase + g)*XP + ks*8;
    const float* p1 = p0 + 8*XP;
    a[0]=tf32r(p0[t]); a[1]=tf32r(p1[t]); a[2]=tf32r(p0[t+4]); a[3]=tf32r(p1[t+4]);
}

// ---------------------------------------------------------------------------
// adj: mask0 has ~5 nonzeros -> compact + gather
// ---------------------------------------------------------------------------
__global__ void adj_kernel(const int* __restrict__ qt,
                           const float* __restrict__ oh,
                           const float* __restrict__ graphs)
{
    __shared__ int   s_idx[CC];
    __shared__ float s_val[CC];
    __shared__ int   s_cnt;
    __shared__ float s_sum;

    int t = threadIdx.x;
    if (t == 0) { s_cnt = 0; s_sum = 0.f; }
    __syncthreads();

    int q0 = qt[0];
    float m = oh[(size_t)q0 * CC + t];
    if (m != 0.f) {
        int p = atomicAdd(&s_cnt, 1);
        s_idx[p] = t; s_val[p] = m;
        atomicAdd(&s_sum, m);
    }
    __syncthreads();

    float denom = fmaxf(s_sum, 1.f);
    int nnz = s_cnt;
    for (int k = 0; k < 2; k++) {
        float acc = 0.f;
        for (int i = 0; i < nnz; i++)
            acc += s_val[i] * graphs[(size_t)k*CC*CC + (size_t)s_idx[i]*CC + t];
        g_adj[k*CC + t] = clampf(acc / denom, -5.f, 5.f);
    }
}

// ---------------------------------------------------------------------------
// kcbase[k][c][j] = bn1[k][j] + sum_e clip(kc[c][e],±5) * Wn1[k][192+e][j]
// ---------------------------------------------------------------------------
__global__ void kcbase_kernel(const float* __restrict__ kc,
                              const float* __restrict__ Wn1,
                              const float* __restrict__ bn1)
{
    __shared__ float skc[64];
    int c = blockIdx.x;
    int tid = threadIdx.x;              // 128
    if (tid < 64) skc[tid] = clampf(kc[c*64 + tid], -5.f, 5.f);
    __syncthreads();
    int k = tid >> 6, j = tid & 63;
    float a = bn1[k*64 + j];
    const float* Wp = Wn1 + k*16384 + 12288 + j;
    #pragma unroll 8
    for (int e = 0; e < 64; e++) a = fmaf(skc[e], Wp[e*64], a);
    g_kcbase[((size_t)k*CC + c)*64 + j] = a;
}

// ---------------------------------------------------------------------------
// f1 (tensor tf32): 128-row tiles, 512 threads, 16 warps = 4rg(32r) x 4cg(16c)
//   Stage A: H1 = relu(kcbase + clip(ht) @ Wn1_ht[k])  (acc init = kcbase)
//   Stage B: nb = clamp(H1 @ Wn2[k] + bn2, 0, 5); nf fold in registers.
// ---------------------------------------------------------------------------
__global__ void __launch_bounds__(512) f1_kernel(
    const int*   __restrict__ qt,  const float* __restrict__ ht,
    const float* __restrict__ oh,  const float* __restrict__ kc,
    const float* __restrict__ nwp,
    const float* __restrict__ Ws1, const float* __restrict__ bs1,
    const float* __restrict__ Ws2, const float* __restrict__ bs2,
    const float* __restrict__ Wn1, const float* __restrict__ Wn2,
    const float* __restrict__ bn2)
{
    extern __shared__ float sm[];
    float*  Xs   = sm;                    // 128*68 = 8704 (clip(ht), raw fp32)
    float*  H1s  = Xs + 8704;             // 8704
    float2* PW1  = (float2*)(H1s + 8704); // [2k][8ks][8nt][32] = 4096 f2 (8192 f)
    float2* PW2  = PW1 + 4096;            // 8192 f
    float*  sbn2 = (float*)(PW2 + 4096);  // 128
    float*  rmask= sbn2 + 128;            // 128
    float*  radj = rmask + 128;           // 256
    float*  xr   = radj + 256;            // 128
    float*  hb   = xr + 128;              // 64
    __shared__ int s_mcnt;
    __shared__ int s_mrows[128];

    int tid = threadIdx.x;
    // one-time fragment packing (both k)
    for (int i = tid; i < 4096; i += 512) {
        int lane = i & 31, nt = (i >> 5) & 7, ks = (i >> 8) & 7, k = i >> 11;
        int t = lane & 3, g = lane >> 2;
        int r0 = ks*8 + t, r1 = r0 + 4, c = nt*8 + g;
        float2 v;
        v.x = __uint_as_float(tf32r(Wn1[k*16384 + (128+r0)*64 + c]));
        v.y = __uint_as_float(tf32r(Wn1[k*16384 + (128+r1)*64 + c]));
        PW1[i] = v;
        v.x = __uint_as_float(tf32r(Wn2[k*4096 + r0*64 + c]));
        v.y = __uint_as_float(tf32r(Wn2[k*4096 + r1*64 + c]));
        PW2[i] = v;
    }
    if (tid < 128) sbn2[tid] = bn2[tid];
    float w = clampf(nwp[0], 0.1f, 0.9f);
    __syncthreads();

    int wid = tid >> 5, lane = tid & 31;
    int rg = wid & 3, cg = wid >> 2;
    int t = lane & 3, g = lane >> 2;
    int rb = rg * 32, cb = cg * 16;

    for (int tile = blockIdx.x; tile < NROWS/128; tile += gridDim.x) {
        int row0 = tile << 7;
        int c0 = row0 & 1023;
        if (tid == 0) s_mcnt = 0;
        __syncthreads();

        // fill Xs = clip(ht) raw fp32 row-major
        for (int i = tid; i < 2048; i += 512) {
            int r = i >> 4, q = i & 15;
            float4 v = *(const float4*)(ht + (size_t)(row0+r)*64 + q*4);
            v.x = clampf(v.x, -5.f, 5.f); v.y = clampf(v.y, -5.f, 5.f);
            v.z = clampf(v.z, -5.f, 5.f); v.w = clampf(v.w, -5.f, 5.f);
            *(float4*)(Xs + r*XP + q*4) = v;
        }
        if (tid < 128) {
            int gid = row0 + tid; int b = gid >> 10; int c = gid & 1023;
            float m = oh[(size_t)qt[b]*CC + c];
            rmask[tid] = m;
            radj[tid]       = g_adj[c];
            radj[128 + tid] = g_adj[CC + c];
            if (m > 0.5f) { int p = atomicAdd(&s_mcnt, 1); s_mrows[p] = tid; }
        }
        __syncthreads();

        float nf[2][2][4];
        #pragma unroll
        for (int k = 0; k < 2; k++) {
            // ---- Stage A: acc init from kcbase, mma over K=64 ----
            float A[2][2][4];
            {
                const float* kcb = g_kcbase + ((size_t)k*CC + c0)*64;
                #pragma unroll
                for (int mt = 0; mt < 2; mt++)
                    #pragma unroll
                    for (int nt = 0; nt < 2; nt++) {
                        int c = cb + nt*8 + 2*t;
                        int rA = rb + mt*16 + g;
                        float2 v0 = *(const float2*)(kcb + rA*64 + c);
                        float2 v1 = *(const float2*)(kcb + (rA+8)*64 + c);
                        A[mt][nt][0]=v0.x; A[mt][nt][1]=v0.y;
                        A[mt][nt][2]=v1.x; A[mt][nt][3]=v1.y;
                    }
            }
            #pragma unroll
            for (int ks = 0; ks < 8; ks++) {
                unsigned f0[4], f1[4];
                ldfragA(f0, Xs, rb,      ks, t, g);
                ldfragA(f1, Xs, rb + 16, ks, t, g);
                #pragma unroll
                for (int nt = 0; nt < 2; nt++) {
                    int bi = ((k*8 + ks)*8 + cg*2 + nt)*32 + lane;
                    float2 bw = PW1[bi];
                    unsigned b0 = __float_as_uint(bw.x), b1 = __float_as_uint(bw.y);
                    mma8(A[0][nt], f0, b0, b1); mma8(A[1][nt], f1, b0, b1);
                }
            }
            // relu -> H1s
            #pragma unroll
            for (int mt = 0; mt < 2; mt++)
                #pragma unroll
                for (int nt = 0; nt < 2; nt++) {
                    int c = cb + nt*8 + 2*t;
                    int rA = rb + mt*16 + g;
                    *(float2*)(H1s + rA*XP + c) =
                        make_float2(fmaxf(A[mt][nt][0],0.f), fmaxf(A[mt][nt][1],0.f));
                    *(float2*)(H1s + (rA+8)*XP + c) =
                        make_float2(fmaxf(A[mt][nt][2],0.f), fmaxf(A[mt][nt][3],0.f));
                }
            __syncthreads();

            // ---- Stage B: nb = clamp(H1 @ Wn2[k] + bn2, 0, 5) ----
            float B[2][2][4];
            #pragma unroll
            for (int mt = 0; mt < 2; mt++)
                #pragma unroll
                for (int nt = 0; nt < 2; nt++) {
                    int c = cb + nt*8 + 2*t;
                    float b0 = sbn2[k*64 + c], b1 = sbn2[k*64 + c + 1];
                    B[mt][nt][0]=b0; B[mt][nt][1]=b1; B[mt][nt][2]=b0; B[mt][nt][3]=b1;
                }
            #pragma unroll
            for (int ks = 0; ks < 8; ks++) {
                unsigned f0[4], f1[4];
                ldfragA(f0, H1s, rb,      ks, t, g);
                ldfragA(f1, H1s, rb + 16, ks, t, g);
                #pragma unroll
                for (int nt = 0; nt < 2; nt++) {
                    int bi = ((k*8 + ks)*8 + cg*2 + nt)*32 + lane;
                    float2 bw = PW2[bi];
                    unsigned b0 = __float_as_uint(bw.x), b1 = __float_as_uint(bw.y);
                    mma8(B[0][nt], f0, b0, b1); mma8(B[1][nt], f1, b0, b1);
                }
            }
            // fold nf
            #pragma unroll
            for (int mt = 0; mt < 2; mt++) {
                int rA = rb + mt*16 + g;
                float a0 = radj[k*128 + rA];
                float a1 = radj[k*128 + rA + 8];
                #pragma unroll
                for (int nt = 0; nt < 2; nt++) {
                    float v0 = a0 * clampf(B[mt][nt][0], 0.f, 5.f);
                    float v1 = a0 * clampf(B[mt][nt][1], 0.f, 5.f);
                    float v2 = a1 * clampf(B[mt][nt][2], 0.f, 5.f);
                    float v3 = a1 * clampf(B[mt][nt][3], 0.f, 5.f);
                    if (k == 0) {
                        nf[mt][nt][0] = clampf(v0, -5.f, 5.f);
                        nf[mt][nt][1] = clampf(v1, -5.f, 5.f);
                        nf[mt][nt][2] = clampf(v2, -5.f, 5.f);
                        nf[mt][nt][3] = clampf(v3, -5.f, 5.f);
                    } else {
                        nf[mt][nt][0] = clampf(w*nf[mt][nt][0] + (1.f-w)*v0, -5.f, 5.f);
                        nf[mt][nt][1] = clampf(w*nf[mt][nt][1] + (1.f-w)*v1, -5.f, 5.f);
                        nf[mt][nt][2] = clampf(w*nf[mt][nt][2] + (1.f-w)*v2, -5.f, 5.f);
                        nf[mt][nt][3] = clampf(w*nf[mt][nt][3] + (1.f-w)*v3, -5.f, 5.f);
                    }
                }
            }
            __syncthreads();   // H1s free for next k
        }

        // write m_next for unmasked rows
        #pragma unroll
        for (int mt = 0; mt < 2; mt++) {
            int rA = rb + mt*16 + g;
            #pragma unroll
            for (int nt = 0; nt < 2; nt++) {
                int c = cb + nt*8 + 2*t;
                if (rmask[rA] <= 0.5f)
                    *(float2*)(&g_mnext[(size_t)(row0+rA)*64 + c]) =
                        make_float2(nf[mt][nt][0], nf[mt][nt][1]);
                if (rmask[rA+8] <= 0.5f)
                    *(float2*)(&g_mnext[(size_t)(row0+rA+8)*64 + c]) =
                        make_float2(nf[mt][nt][2], nf[mt][nt][3]);
            }
        }

        // rare masked rows: self MLP on RAW [ht, kc] (exact fp32)
        int mcnt = s_mcnt;
        for (int mi = 0; mi < mcnt; mi++) {
            int r = s_mrows[mi]; int gid = row0 + r; int c = gid & 1023;
            if (tid < 128)
                xr[tid] = (tid < 64) ? ht[(size_t)gid*64 + tid] : kc[c*64 + tid - 64];
            __syncthreads();
            if (tid < 64) {
                float a = bs1[tid];
                for (int j = 0; j < 128; j++) a = fmaf(xr[j], Ws1[j*64 + tid], a);
                hb[tid] = fmaxf(a, 0.f);
            }
            __syncthreads();
            if (tid < 64) {
                float a = bs2[tid];
                for (int j = 0; j < 64; j++) a = fmaf(hb[j], Ws2[j*64 + tid], a);
                g_mnext[(size_t)gid*64 + tid] = clampf(a, 0.f, 10.f);
            }
            __syncthreads();
        }
        __syncthreads();
    }
}

// ---------------------------------------------------------------------------
// f2 (tensor-core tf32, unchanged from R7)
// ---------------------------------------------------------------------------
__global__ void __launch_bounds__(512) f2_kernel(
    const float* __restrict__ ht,  const float* __restrict__ ea_w,
    const float* __restrict__ We,  const float* __restrict__ be,
    const float* __restrict__ Wa,  const float* __restrict__ ba,
    const float* __restrict__ Wih, const float* __restrict__ bih,
    const float* __restrict__ Whh, const float* __restrict__ bhh,
    const float* __restrict__ Wp,  const float* __restrict__ bp,
    float* __restrict__ out)
{
    extern __shared__ float sm[];
    float*  Xs   = sm;                       // 8704 (m, then res)
    float*  Hs   = Xs + 8704;                // 8704 (ht)
    float2* PWe  = (float2*)(Hs + 8704);     // 2048 f2
    float2* PWa  = PWe + 2048;
    float2* PWih = PWa + 2048;               // 6144 f2
    float2* PWhh = PWih + 6144;
    float*  sbe  = (float*)(PWhh + 6144);
    float*  sba  = sbe + 64;
    float*  sbrz = sba + 64;
    float*  sbI  = sbrz + 128;
    float*  sbH  = sbI + 64;
    float*  sWp  = sbH + 64;
    float*  sred = sWp + 64;                 // 512

    int tid = threadIdx.x;

    for (int i = tid; i < 2048; i += 512) {
        int lane = i & 31, nt = (i >> 5) & 7, ks = i >> 8;
        int t = lane & 3, g = lane >> 2;
        int r0 = ks*8 + t, r1 = r0 + 4, c = nt*8 + g;
        float2 v;
        v.x = __uint_as_float(tf32r(We[r0*64 + c]));
        v.y = __uint_as_float(tf32r(We[r1*64 + c]));
        PWe[i] = v;
        v.x = __uint_as_float(tf32r(Wa[r0*64 + c]));
        v.y = __uint_as_float(tf32r(Wa[r1*64 + c]));
        PWa[i] = v;
    }
    for (int i = tid; i < 6144; i += 512) {
        int lane = i & 31; int rest = i >> 5; int nt = rest % 24, ks = rest / 24;
        int t = lane & 3, g = lane >> 2;
        int r0 = ks*8 + t, r1 = r0 + 4, c = nt*8 + g;
        float2 v;
        v.x = __uint_as_float(tf32r(Wih[r0*192 + c]));
        v.y = __uint_as_float(tf32r(Wih[r1*192 + c]));
        PWih[i] = v;
        v.x = __uint_as_float(tf32r(Whh[r0*192 + c]));
        v.y = __uint_as_float(tf32r(Whh[r1*192 + c]));
        PWhh[i] = v;
    }
    if (tid < 64) {
        sbe[tid] = be[tid]; sba[tid] = ba[tid]; sWp[tid] = Wp[tid];
        sbI[tid] = bih[128 + tid]; sbH[tid] = bhh[128 + tid];
    }
    if (tid < 128) sbrz[tid] = bih[tid] + bhh[tid];
    float bpv = bp[0];
    __syncthreads();

    int wid = tid >> 5, lane = tid & 31;
    int rg = wid & 3, cg = wid >> 2;
    int t = lane & 3, g = lane >> 2;
    int rb = rg * 32, cb = cg * 16;

    for (int tile = blockIdx.x; tile < NROWS/128; tile += gridDim.x) {
        int row0 = tile << 7;

        for (int i = tid; i < 2048; i += 512) {
            int r = i >> 4, q = i & 15;
            float4 m4 = *(const float4*)(g_mnext + (size_t)(row0+r)*64 + q*4);
            float4 h4 = *(const float4*)(ht      + (size_t)(row0+r)*64 + q*4);
            *(float4*)(Xs + r*XP + q*4) = m4;
            *(float4*)(Hs + r*XP + q*4) = h4;
        }
        __syncthreads();

        // ---- Phase A ----
        float S[2][2][4], T[2][2][4];
        #pragma unroll
        for (int mt = 0; mt < 2; mt++)
            #pragma unroll
            for (int nt = 0; nt < 2; nt++) {
                int c = cb + nt*8 + 2*t;
                S[mt][nt][0]=sbe[c]; S[mt][nt][1]=sbe[c+1]; S[mt][nt][2]=sbe[c]; S[mt][nt][3]=sbe[c+1];
                T[mt][nt][0]=sba[c]; T[mt][nt][1]=sba[c+1]; T[mt][nt][2]=sba[c]; T[mt][nt][3]=sba[c+1];
            }
        #pragma unroll
        for (int ks = 0; ks < 8; ks++) {
            unsigned f0[4], f1[4];
            ldfragA(f0, Xs, rb,      ks, t, g);
            ldfragA(f1, Xs, rb + 16, ks, t, g);
            #pragma unroll
            for (int nt = 0; nt < 2; nt++) {
                int bi = (ks*8 + cg*2 + nt)*32 + lane;
                float2 bw = PWe[bi];
                unsigned b0 = __float_as_uint(bw.x), b1 = __float_as_uint(bw.y);
                mma8(S[0][nt], f0, b0, b1); mma8(S[1][nt], f1, b0, b1);
                bw = PWa[bi];
                b0 = __float_as_uint(bw.x); b1 = __float_as_uint(bw.y);
                mma8(T[0][nt], f0, b0, b1); mma8(T[1][nt], f1, b0, b1);
            }
        }

        float resv[2][2][4];
        float ga[4];
        #pragma unroll
        for (int q = 0; q < 4; q++)
            ga[q] = ea_w[(row0 + rb + (q>>1)*16 + (q&1)*8 + g) & 1023];
        #pragma unroll
        for (int mt = 0; mt < 2; mt++)
            #pragma unroll
            for (int nt = 0; nt < 2; nt++) {
                int c = cb + nt*8 + 2*t;
                int rA = rb + mt*16 + g;
                float2 m0 = *(const float2*)(Xs + rA*XP + c);
                float2 m1 = *(const float2*)(Xs + (rA+8)*XP + c);
                float g0 = ga[2*mt], g1 = ga[2*mt+1];
                resv[mt][nt][0] = m0.x - g0*sigf(S[mt][nt][0])*m0.x + g0*tanhfast(T[mt][nt][0]);
                resv[mt][nt][1] = m0.y - g0*sigf(S[mt][nt][1])*m0.y + g0*tanhfast(T[mt][nt][1]);
                resv[mt][nt][2] = m1.x - g1*sigf(S[mt][nt][2])*m1.x + g1*tanhfast(T[mt][nt][2]);
                resv[mt][nt][3] = m1.y - g1*sigf(S[mt][nt][3])*m1.y + g1*tanhfast(T[mt][nt][3]);
            }
        __syncthreads();
        #pragma unroll
        for (int mt = 0; mt < 2; mt++)
            #pragma unroll
            for (int nt = 0; nt < 2; nt++) {
                int c = cb + nt*8 + 2*t;
                int rA = rb + mt*16 + g;
                *(float2*)(Xs + rA*XP + c)     = make_float2(resv[mt][nt][0], resv[mt][nt][1]);
                *(float2*)(Xs + (rA+8)*XP + c) = make_float2(resv[mt][nt][2], resv[mt][nt][3]);
            }
        __syncthreads();

        // ---- Phase BC ----
        float R[2][2][4], Z[2][2][4], I_[2][2][4], Hh[2][2][4];
        #pragma unroll
        for (int mt = 0; mt < 2; mt++)
            #pragma unroll
            for (int nt = 0; nt < 2; nt++) {
                int c = cb + nt*8 + 2*t;
                R[mt][nt][0]=sbrz[c];    R[mt][nt][1]=sbrz[c+1];    R[mt][nt][2]=sbrz[c];    R[mt][nt][3]=sbrz[c+1];
                Z[mt][nt][0]=sbrz[64+c]; Z[mt][nt][1]=sbrz[64+c+1]; Z[mt][nt][2]=sbrz[64+c]; Z[mt][nt][3]=sbrz[64+c+1];
                I_[mt][nt][0]=sbI[c];    I_[mt][nt][1]=sbI[c+1];    I_[mt][nt][2]=sbI[c];    I_[mt][nt][3]=sbI[c+1];
                Hh[mt][nt][0]=sbH[c];    Hh[mt][nt][1]=sbH[c+1];    Hh[mt][nt][2]=sbH[c];    Hh[mt][nt][3]=sbH[c+1];
            }
        #pragma unroll
        for (int ks = 0; ks < 8; ks++) {
            unsigned f0[4], f1[4];
            ldfragA(f0, Xs, rb,      ks, t, g);
            ldfragA(f1, Xs, rb + 16, ks, t, g);
            #pragma unroll
            for (int nt = 0; nt < 2; nt++) {
                int bi = (ks*24 + cg*2 + nt)*32 + lane;
                float2 bw = PWih[bi];
                unsigned b0 = __float_as_uint(bw.x), b1 = __float_as_uint(bw.y);
                mma8(R[0][nt], f0, b0, b1); mma8(R[1][nt], f1, b0, b1);
                bw = PWih[bi + 256];
                b0 = __float_as_uint(bw.x); b1 = __float_as_uint(bw.y);
                mma8(Z[0][nt], f0, b0, b1); mma8(Z[1][nt], f1, b0, b1);
                bw = PWih[bi + 512];
                b0 = __float_as_uint(bw.x); b1 = __float_as_uint(bw.y);
                mma8(I_[0][nt], f0, b0, b1); mma8(I_[1][nt], f1, b0, b1);
            }
            ldfragA(f0, Hs, rb,      ks, t, g);
            ldfragA(f1, Hs, rb + 16, ks, t, g);
            #pragma unroll
            for (int nt = 0; nt < 2; nt++) {
                int bi = (ks*24 + cg*2 + nt)*32 + lane;
                float2 bw = PWhh[bi];
                unsigned b0 = __float_as_uint(bw.x), b1 = __float_as_uint(bw.y);
                mma8(R[0][nt], f0, b0, b1); mma8(R[1][nt], f1, b0, b1);
                bw = PWhh[bi + 256];
                b0 = __float_as_uint(bw.x); b1 = __float_as_uint(bw.y);
                mma8(Z[0][nt], f0, b0, b1); mma8(Z[1][nt], f1, b0, b1);
                bw = PWhh[bi + 512];
                b0 = __float_as_uint(bw.x); b1 = __float_as_uint(bw.y);
                mma8(Hh[0][nt], f0, b0, b1); mma8(Hh[1][nt], f1, b0, b1);
            }
        }

        float py[4] = {0.f, 0.f, 0.f, 0.f};
        #pragma unroll
        for (int mt = 0; mt < 2; mt++)
            #pragma unroll
            for (int nt = 0; nt < 2; nt++) {
                int c = cb + nt*8 + 2*t;
                int rA = rb + mt*16 + g;
                float2 h0 = *(const float2*)(Hs + rA*XP + c);
                float2 h1 = *(const float2*)(Hs + (rA+8)*XP + c);
                float wc0 = sWp[c], wc1 = sWp[c+1];
                {
                    float rr = sigf(R[mt][nt][0]), zz = sigf(Z[mt][nt][0]);
                    float nn = tanhfast(I_[mt][nt][0] + rr*Hh[mt][nt][0]);
                    py[2*mt] = fmaf((1.f-zz)*nn + zz*h0.x, wc0, py[2*mt]);
                }
                {
                    float rr = sigf(R[mt][nt][1]), zz = sigf(Z[mt][nt][1]);
                    float nn = tanhfast(I_[mt][nt][1] + rr*Hh[mt][nt][1]);
                    py[2*mt] = fmaf((1.f-zz)*nn + zz*h0.y, wc1, py[2*mt]);
                }
                {
                    float rr = sigf(R[mt][nt][2]), zz = sigf(Z[mt][nt][2]);
                    float nn = tanhfast(I_[mt][nt][2] + rr*Hh[mt][nt][2]);
                    py[2*mt+1] = fmaf((1.f-zz)*nn + zz*h1.x, wc0, py[2*mt+1]);
                }
                {
                    float rr = sigf(R[mt][nt][3]), zz = sigf(Z[mt][nt][3]);
                    float nn = tanhfast(I_[mt][nt][3] + rr*Hh[mt][nt][3]);
                    py[2*mt+1] = fmaf((1.f-zz)*nn + zz*h1.y, wc1, py[2*mt+1]);
                }
            }
        #pragma unroll
        for (int q = 0; q < 4; q++) {
            py[q] += __shfl_xor_sync(0xffffffffu, py[q], 1, 4);
            py[q] += __shfl_xor_sync(0xffffffffu, py[q], 2, 4);
        }
        if (t == 0) {
            sred[cg*128 + rb + g]      = py[0];
            sred[cg*128 + rb + 8 + g]  = py[1];
            sred[cg*128 + rb + 16 + g] = py[2];
            sred[cg*128 + rb + 24 + g] = py[3];
        }
        __syncthreads();
        if (tid < 128)
            out[row0 + tid] = sigf(sred[tid] + sred[128+tid] + sred[256+tid] + sred[384+tid] + bpv);
        __syncthreads();
    }
}

// ---------------------------------------------------------------------------
extern "C" void kernel_launch(void* const* d_in, const int* in_sizes, int n_in,
                              void* d_out, int out_size)
{
    const int*   qt  = (const int*)  d_in[1];
    const float* ht  = (const float*)d_in[2];
    const float* oh  = (const float*)d_in[3];
    const float* kc  = (const float*)d_in[4];
    const float* gr  = (const float*)d_in[5];
    const float* nw  = (const float*)d_in[6];
    const float* Ws1 = (const float*)d_in[7];
    const float* bs1 = (const float*)d_in[8];
    const float* Ws2 = (const float*)d_in[9];
    const float* bs2 = (const float*)d_in[10];
    const float* Wn1 = (const float*)d_in[11];
    const float* bn1 = (const float*)d_in[12];
    const float* Wn2 = (const float*)d_in[13];
    const float* bn2 = (const float*)d_in[14];
    const float* ea  = (const float*)d_in[15];
    const float* We  = (const float*)d_in[16];
    const float* be  = (const float*)d_in[17];
    const float* Wa  = (const float*)d_in[18];
    const float* ba  = (const float*)d_in[19];
    const float* Wih = (const float*)d_in[20];
    const float* bih = (const float*)d_in[21];
    const float* Whh = (const float*)d_in[22];
    const float* bhh = (const float*)d_in[23];
    const float* Wp  = (const float*)d_in[24];
    const float* bp  = (const float*)d_in[25];
    float* out = (float*)d_out;

    int smc = 148;
    if (cudaDeviceGetAttribute(&smc, cudaDevAttrMultiProcessorCount, 0) != cudaSuccess || smc <= 0)
        smc = 148;

    size_t smem1 = (size_t)(8704+8704+8192+8192+128+128+256+128+64+64) * 4;  // ~138 KB
    size_t smem2 = (size_t)51136 * 4;                                        // 204544 B
    cudaFuncSetAttribute(f1_kernel, cudaFuncAttributeMaxDynamicSharedMemorySize, (int)smem1);
    cudaFuncSetAttribute(f2_kernel, cudaFuncAttributeMaxDynamicSharedMemorySize, (int)smem2);

    adj_kernel<<<1, 1024>>>(qt, oh, gr);
    kcbase_kernel<<<1024, 128>>>(kc, Wn1, bn1);
    f1_kernel<<<smc, 512, smem1>>>(qt, ht, oh, kc, nw, Ws1, bs1, Ws2, bs2, Wn1, Wn2, bn2);
    f2_kernel<<<smc, 512, smem2>>>(ht, ea, We, be, Wa, ba, Wih, bih, Whh, bhh, Wp, bp, out);
}

// round 9
// speedup vs baseline: 1.9749x; 1.0708x over previous
#include <cuda_runtime.h>
#include <cstdint>
#include <math.h>

#define CC 1024
#define NROWS (256*1024)
#define XP  68      // row-major pad (bank-spread for fragment gathers)

typedef unsigned long long ull;

// Scratch (allocation-free rule: __device__ globals)
__device__ float g_adj[2*CC];
__device__ float g_kcbase[2*CC*64];
__device__ float g_mnext[(size_t)NROWS * 64];

__device__ __forceinline__ float clampf(float v,float lo,float hi){ return fminf(fmaxf(v,lo),hi); }
__device__ __forceinline__ float sigf(float x){ return __fdividef(1.f, 1.f + __expf(-x)); }
__device__ __forceinline__ float tanhfast(float x){
    float t = __expf(-2.f*fabsf(x));
    float r = __fdividef(1.f - t, 1.f + t);
    return copysignf(r, x);
}

// ---- tf32 helpers -----------------------------------------------------------
__device__ __forceinline__ unsigned tf32r(float f){
    unsigned u; asm("cvt.rna.tf32.f32 %0, %1;" : "=r"(u) : "f"(f)); return u;
}
__device__ __forceinline__ float tf32f(float f){ return __uint_as_float(tf32r(f)); }
__device__ __forceinline__ void mma8(float c[4], const unsigned a[4], unsigned b0, unsigned b1){
    asm volatile(
        "mma.sync.aligned.m16n8k8.row.col.f32.tf32.tf32.f32 "
        "{%0,%1,%2,%3},{%4,%5,%6,%7},{%8,%9},{%0,%1,%2,%3};"
        : "+f"(c[0]),"+f"(c[1]),"+f"(c[2]),"+f"(c[3])
        : "r"(a[0]),"r"(a[1]),"r"(a[2]),"r"(a[3]),"r"(b0),"r"(b1));
}
// A fragment (16x8) from PRE-ROUNDED tf32 smem — no cvt.
__device__ __forceinline__ void ldfragA_nc(unsigned a[4], const float* X, int rowbase, int ks, int t, int g){
    const float* p0 = X + (rowbase + g)*XP + ks*8;
    const float* p1 = p0 + 8*XP;
    a[0]=__float_as_uint(p0[t]);   a[1]=__float_as_uint(p1[t]);
    a[2]=__float_as_uint(p0[t+4]); a[3]=__float_as_uint(p1[t+4]);
}

// ---------------------------------------------------------------------------
// adj: mask0 has ~5 nonzeros -> compact + gather
// ---------------------------------------------------------------------------
__global__ void adj_kernel(const int* __restrict__ qt,
                           const float* __restrict__ oh,
                           const float* __restrict__ graphs)
{
    __shared__ int   s_idx[CC];
    __shared__ float s_val[CC];
    __shared__ int   s_cnt;
    __shared__ float s_sum;

    int t = threadIdx.x;
    if (t == 0) { s_cnt = 0; s_sum = 0.f; }
    __syncthreads();

    int q0 = qt[0];
    float m = oh[(size_t)q0 * CC + t];
    if (m != 0.f) {
        int p = atomicAdd(&s_cnt, 1);
        s_idx[p] = t; s_val[p] = m;
        atomicAdd(&s_sum, m);
    }
    __syncthreads();

    float denom = fmaxf(s_sum, 1.f);
    int nnz = s_cnt;
    for (int k = 0; k < 2; k++) {
        float acc = 0.f;
        for (int i = 0; i < nnz; i++)
            acc += s_val[i] * graphs[(size_t)k*CC*CC + (size_t)s_idx[i]*CC + t];
        g_adj[k*CC + t] = clampf(acc / denom, -5.f, 5.f);
    }
}

// ---------------------------------------------------------------------------
// kcbase[k][c][j] = bn1[k][j] + sum_e clip(kc[c][e],±5) * Wn1[k][192+e][j]
// ---------------------------------------------------------------------------
__global__ void kcbase_kernel(const float* __restrict__ kc,
                              const float* __restrict__ Wn1,
                              const float* __restrict__ bn1)
{
    __shared__ float skc[64];
    int c = blockIdx.x;
    int tid = threadIdx.x;              // 128
    if (tid < 64) skc[tid] = clampf(kc[c*64 + tid], -5.f, 5.f);
    __syncthreads();
    int k = tid >> 6, j = tid & 63;
    float a = bn1[k*64 + j];
    const float* Wp = Wn1 + k*16384 + 12288 + j;
    #pragma unroll 8
    for (int e = 0; e < 64; e++) a = fmaf(skc[e], Wp[e*64], a);
    g_kcbase[((size_t)k*CC + c)*64 + j] = a;
}

// ---------------------------------------------------------------------------
// f1 (tensor tf32, k-merged, no mask logic): 128-row tiles, 512 threads.
// Stage A (both k): H1[k] = relu(kcbase[k] + clip(ht) @ Wn1_ht[k]); one sync.
// Stage B (both k): nb[k] = clamp(H1[k] @ Wn2[k] + bn2[k], 0, 5); nf fold.
// Writes ALL rows (masked rows fixed afterward by selfmlp_kernel).
// ---------------------------------------------------------------------------
__global__ void __launch_bounds__(512) f1_kernel(
    const float* __restrict__ ht,  const float* __restrict__ nwp,
    const float* __restrict__ Wn1, const float* __restrict__ Wn2,
    const float* __restrict__ bn2)
{
    extern __shared__ float sm[];
    float*  Xs   = sm;                    // 8704 (tf32-rounded clip(ht))
    float*  H1s  = Xs + 8704;             // 2*8704 = 17408 (k=0, k=1)
    float2* PW1  = (float2*)(H1s + 17408);// 4096 f2 (8192 f)
    float2* PW2  = PW1 + 4096;            // 8192 f
    float*  sbn2 = (float*)(PW2 + 4096);  // 128
    float*  radj = sbn2 + 128;            // 256

    int tid = threadIdx.x;
    for (int i = tid; i < 4096; i += 512) {
        int lane = i & 31, nt = (i >> 5) & 7, ks = (i >> 8) & 7, k = i >> 11;
        int t = lane & 3, g = lane >> 2;
        int r0 = ks*8 + t, r1 = r0 + 4, c = nt*8 + g;
        float2 v;
        v.x = __uint_as_float(tf32r(Wn1[k*16384 + (128+r0)*64 + c]));
        v.y = __uint_as_float(tf32r(Wn1[k*16384 + (128+r1)*64 + c]));
        PW1[i] = v;
        v.x = __uint_as_float(tf32r(Wn2[k*4096 + r0*64 + c]));
        v.y = __uint_as_float(tf32r(Wn2[k*4096 + r1*64 + c]));
        PW2[i] = v;
    }
    if (tid < 128) sbn2[tid] = bn2[tid];
    float w = clampf(nwp[0], 0.1f, 0.9f);
    __syncthreads();

    int wid = tid >> 5, lane = tid & 31;
    int rg = wid & 3, cg = wid >> 2;
    int t = lane & 3, g = lane >> 2;
    int rb = rg * 32, cb = cg * 16;

    for (int tile = blockIdx.x; tile < NROWS/128; tile += gridDim.x) {
        int row0 = tile << 7;
        int c0 = row0 & 1023;

        // fill Xs = tf32(clip(ht)); radj
        for (int i = tid; i < 2048; i += 512) {
            int r = i >> 4, q = i & 15;
            float4 v = *(const float4*)(ht + (size_t)(row0+r)*64 + q*4);
            v.x = tf32f(clampf(v.x, -5.f, 5.f)); v.y = tf32f(clampf(v.y, -5.f, 5.f));
            v.z = tf32f(clampf(v.z, -5.f, 5.f)); v.w = tf32f(clampf(v.w, -5.f, 5.f));
            *(float4*)(Xs + r*XP + q*4) = v;
        }
        if (tid < 128) {
            int c = (row0 + tid) & 1023;
            radj[tid]       = g_adj[c];
            radj[128 + tid] = g_adj[CC + c];
        }
        __syncthreads();

        // ---- Stage A (both k): acc init from kcbase ----
        float A[2][2][2][4];   // [k][mt][nt][4]
        #pragma unroll
        for (int k = 0; k < 2; k++) {
            const float* kcb = g_kcbase + ((size_t)k*CC + c0)*64;
            #pragma unroll
            for (int mt = 0; mt < 2; mt++)
                #pragma unroll
                for (int nt = 0; nt < 2; nt++) {
                    int c = cb + nt*8 + 2*t;
                    int rA = rb + mt*16 + g;
                    float2 v0 = *(const float2*)(kcb + rA*64 + c);
                    float2 v1 = *(const float2*)(kcb + (rA+8)*64 + c);
                    A[k][mt][nt][0]=v0.x; A[k][mt][nt][1]=v0.y;
                    A[k][mt][nt][2]=v1.x; A[k][mt][nt][3]=v1.y;
                }
        }
        #pragma unroll
        for (int ks = 0; ks < 8; ks++) {
            unsigned f0[4], f1v[4];
            ldfragA_nc(f0,  Xs, rb,      ks, t, g);
            ldfragA_nc(f1v, Xs, rb + 16, ks, t, g);
            #pragma unroll
            for (int k = 0; k < 2; k++)
                #pragma unroll
                for (int nt = 0; nt < 2; nt++) {
                    int bi = ((k*8 + ks)*8 + cg*2 + nt)*32 + lane;
                    float2 bw = PW1[bi];
                    unsigned b0 = __float_as_uint(bw.x), b1 = __float_as_uint(bw.y);
                    mma8(A[k][0][nt], f0,  b0, b1);
                    mma8(A[k][1][nt], f1v, b0, b1);
                }
        }
        // relu + tf32-round -> H1s[k]
        #pragma unroll
        for (int k = 0; k < 2; k++) {
            float* H = H1s + k*8704;
            #pragma unroll
            for (int mt = 0; mt < 2; mt++)
                #pragma unroll
                for (int nt = 0; nt < 2; nt++) {
                    int c = cb + nt*8 + 2*t;
                    int rA = rb + mt*16 + g;
                    *(float2*)(H + rA*XP + c) =
                        make_float2(tf32f(fmaxf(A[k][mt][nt][0],0.f)), tf32f(fmaxf(A[k][mt][nt][1],0.f)));
                    *(float2*)(H + (rA+8)*XP + c) =
                        make_float2(tf32f(fmaxf(A[k][mt][nt][2],0.f)), tf32f(fmaxf(A[k][mt][nt][3],0.f)));
                }
        }
        __syncthreads();

        // ---- Stage B (both k) ----
        float B[2][2][2][4];
        #pragma unroll
        for (int k = 0; k < 2; k++)
            #pragma unroll
            for (int mt = 0; mt < 2; mt++)
                #pragma unroll
                for (int nt = 0; nt < 2; nt++) {
                    int c = cb + nt*8 + 2*t;
                    float b0 = sbn2[k*64 + c], b1 = sbn2[k*64 + c + 1];
                    B[k][mt][nt][0]=b0; B[k][mt][nt][1]=b1; B[k][mt][nt][2]=b0; B[k][mt][nt][3]=b1;
                }
        #pragma unroll
        for (int ks = 0; ks < 8; ks++) {
            unsigned e0[4], e1[4], e2[4], e3[4];
            ldfragA_nc(e0, H1s,        rb,      ks, t, g);
            ldfragA_nc(e1, H1s,        rb + 16, ks, t, g);
            ldfragA_nc(e2, H1s + 8704, rb,      ks, t, g);
            ldfragA_nc(e3, H1s + 8704, rb + 16, ks, t, g);
            #pragma unroll
            for (int nt = 0; nt < 2; nt++) {
                int bi0 = ((0*8 + ks)*8 + cg*2 + nt)*32 + lane;
                int bi1 = ((1*8 + ks)*8 + cg*2 + nt)*32 + lane;
                float2 bw = PW2[bi0];
                unsigned b0 = __float_as_uint(bw.x), b1 = __float_as_uint(bw.y);
                mma8(B[0][0][nt], e0, b0, b1); mma8(B[0][1][nt], e1, b0, b1);
                bw = PW2[bi1];
                b0 = __float_as_uint(bw.x); b1 = __float_as_uint(bw.y);
                mma8(B[1][0][nt], e2, b0, b1); mma8(B[1][1][nt], e3, b0, b1);
            }
        }

        // fold nf + write ALL rows (tf32-rounded for downstream no-cvt loads)
        #pragma unroll
        for (int mt = 0; mt < 2; mt++) {
            int rA = rb + mt*16 + g;
            float a00 = radj[rA],       a01 = radj[rA + 8];
            float a10 = radj[128 + rA], a11 = radj[128 + rA + 8];
            #pragma unroll
            for (int nt = 0; nt < 2; nt++) {
                int c = cb + nt*8 + 2*t;
                float n0 = clampf(a00 * clampf(B[0][mt][nt][0], 0.f, 5.f), -5.f, 5.f);
                float n1 = clampf(a00 * clampf(B[0][mt][nt][1], 0.f, 5.f), -5.f, 5.f);
                float n2 = clampf(a01 * clampf(B[0][mt][nt][2], 0.f, 5.f), -5.f, 5.f);
                float n3 = clampf(a01 * clampf(B[0][mt][nt][3], 0.f, 5.f), -5.f, 5.f);
                float u0 = a10 * clampf(B[1][mt][nt][0], 0.f, 5.f);
                float u1 = a10 * clampf(B[1][mt][nt][1], 0.f, 5.f);
                float u2 = a11 * clampf(B[1][mt][nt][2], 0.f, 5.f);
                float u3 = a11 * clampf(B[1][mt][nt][3], 0.f, 5.f);
                n0 = clampf(w*n0 + (1.f-w)*u0, -5.f, 5.f);
                n1 = clampf(w*n1 + (1.f-w)*u1, -5.f, 5.f);
                n2 = clampf(w*n2 + (1.f-w)*u2, -5.f, 5.f);
                n3 = clampf(w*n3 + (1.f-w)*u3, -5.f, 5.f);
                *(float2*)(&g_mnext[(size_t)(row0+rA)*64 + c])   = make_float2(tf32f(n0), tf32f(n1));
                *(float2*)(&g_mnext[(size_t)(row0+rA+8)*64 + c]) = make_float2(tf32f(n2), tf32f(n3));
            }
        }
        __syncthreads();   // before next tile overwrites Xs/H1s
    }
}

// ---------------------------------------------------------------------------
// selfmlp fix: overwrite masked rows with clip(relu-MLP([ht,kc])) (exact fp32).
// One block per batch row; ~5 masked cols each.
// ---------------------------------------------------------------------------
__global__ void __launch_bounds__(128) selfmlp_kernel(
    const int* __restrict__ qt,  const float* __restrict__ oh,
    const float* __restrict__ ht, const float* __restrict__ kc,
    const float* __restrict__ Ws1, const float* __restrict__ bs1,
    const float* __restrict__ Ws2, const float* __restrict__ bs2)
{
    __shared__ int s_idx[CC];
    __shared__ int s_cnt;
    __shared__ float xr[128];
    __shared__ float hb[64];

    int b = blockIdx.x, tid = threadIdx.x;
    if (tid == 0) s_cnt = 0;
    __syncthreads();
    int q = qt[b];
    for (int c = tid; c < CC; c += 128)
        if (oh[(size_t)q*CC + c] > 0.5f) { int p = atomicAdd(&s_cnt, 1); s_idx[p] = c; }
    __syncthreads();
    int n = s_cnt;
    for (int i = 0; i < n; i++) {
        int c = s_idx[i];
        size_t gid = (size_t)b*CC + c;
        xr[tid] = (tid < 64) ? ht[gid*64 + tid] : kc[c*64 + tid - 64];
        __syncthreads();
        if (tid < 64) {
            float a = bs1[tid];
            #pragma unroll 8
            for (int j = 0; j < 128; j++) a = fmaf(xr[j], Ws1[j*64 + tid], a);
            hb[tid] = fmaxf(a, 0.f);
        }
        __syncthreads();
        if (tid < 64) {
            float a = bs2[tid];
            #pragma unroll 8
            for (int j = 0; j < 64; j++) a = fmaf(hb[j], Ws2[j*64 + tid], a);
            a = clampf(a, 0.f, 10.f);
            g_mnext[gid*64 + tid] = tf32f(a);
        }
        __syncthreads();
    }
}

// ---------------------------------------------------------------------------
// f2 (tensor tf32, no-cvt fragment loads; Xs/Hs hold tf32-rounded values)
// ---------------------------------------------------------------------------
__global__ void __launch_bounds__(512) f2_kernel(
    const float* __restrict__ ht,  const float* __restrict__ ea_w,
    const float* __restrict__ We,  const float* __restrict__ be,
    const float* __restrict__ Wa,  const float* __restrict__ ba,
    const float* __restrict__ Wih, const float* __restrict__ bih,
    const float* __restrict__ Whh, const float* __restrict__ bhh,
    const float* __restrict__ Wp,  const float* __restrict__ bp,
    float* __restrict__ out)
{
    extern __shared__ float sm[];
    float*  Xs   = sm;                       // 8704 (m tf32, then res tf32)
    float*  Hs   = Xs + 8704;                // 8704 (ht tf32)
    float2* PWe  = (float2*)(Hs + 8704);     // 2048 f2
    float2* PWa  = PWe + 2048;
    float2* PWih = PWa + 2048;               // 6144 f2
    float2* PWhh = PWih + 6144;
    float*  sbe  = (float*)(PWhh + 6144);
    float*  sba  = sbe + 64;
    float*  sbrz = sba + 64;
    float*  sbI  = sbrz + 128;
    float*  sbH  = sbI + 64;
    float*  sWp  = sbH + 64;
    float*  sred = sWp + 64;                 // 512

    int tid = threadIdx.x;

    for (int i = tid; i < 2048; i += 512) {
        int lane = i & 31, nt = (i >> 5) & 7, ks = i >> 8;
        int t = lane & 3, g = lane >> 2;
        int r0 = ks*8 + t, r1 = r0 + 4, c = nt*8 + g;
        float2 v;
        v.x = __uint_as_float(tf32r(We[r0*64 + c]));
        v.y = __uint_as_float(tf32r(We[r1*64 + c]));
        PWe[i] = v;
        v.x = __uint_as_float(tf32r(Wa[r0*64 + c]));
        v.y = __uint_as_float(tf32r(Wa[r1*64 + c]));
        PWa[i] = v;
    }
    for (int i = tid; i < 6144; i += 512) {
        int lane = i & 31; int rest = i >> 5; int nt = rest % 24, ks = rest / 24;
        int t = lane & 3, g = lane >> 2;
        int r0 = ks*8 + t, r1 = r0 + 4, c = nt*8 + g;
        float2 v;
        v.x = __uint_as_float(tf32r(Wih[r0*192 + c]));
        v.y = __uint_as_float(tf32r(Wih[r1*192 + c]));
        PWih[i] = v;
        v.x = __uint_as_float(tf32r(Whh[r0*192 + c]));
        v.y = __uint_as_float(tf32r(Whh[r1*192 + c]));
        PWhh[i] = v;
    }
    if (tid < 64) {
        sbe[tid] = be[tid]; sba[tid] = ba[tid]; sWp[tid] = Wp[tid];
        sbI[tid] = bih[128 + tid]; sbH[tid] = bhh[128 + tid];
    }
    if (tid < 128) sbrz[tid] = bih[tid] + bhh[tid];
    float bpv = bp[0];
    __syncthreads();

    int wid = tid >> 5, lane = tid & 31;
    int rg = wid & 3, cg = wid >> 2;
    int t = lane & 3, g = lane >> 2;
    int rb = rg * 32, cb = cg * 16;

    for (int tile = blockIdx.x; tile < NROWS/128; tile += gridDim.x) {
        int row0 = tile << 7;

        for (int i = tid; i < 2048; i += 512) {
            int r = i >> 4, q = i & 15;
            float4 m4 = *(const float4*)(g_mnext + (size_t)(row0+r)*64 + q*4);  // already tf32
            float4 h4 = *(const float4*)(ht      + (size_t)(row0+r)*64 + q*4);
            h4.x = tf32f(h4.x); h4.y = tf32f(h4.y); h4.z = tf32f(h4.z); h4.w = tf32f(h4.w);
            *(float4*)(Xs + r*XP + q*4) = m4;
            *(float4*)(Hs + r*XP + q*4) = h4;
        }
        __syncthreads();

        // ---- Phase A ----
        float S[2][2][4], T[2][2][4];
        #pragma unroll
        for (int mt = 0; mt < 2; mt++)
            #pragma unroll
            for (int nt = 0; nt < 2; nt++) {
                int c = cb + nt*8 + 2*t;
                S[mt][nt][0]=sbe[c]; S[mt][nt][1]=sbe[c+1]; S[mt][nt][2]=sbe[c]; S[mt][nt][3]=sbe[c+1];
                T[mt][nt][0]=sba[c]; T[mt][nt][1]=sba[c+1]; T[mt][nt][2]=sba[c]; T[mt][nt][3]=sba[c+1];
            }
        #pragma unroll
        for (int ks = 0; ks < 8; ks++) {
            unsigned f0[4], f1[4];
            ldfragA_nc(f0, Xs, rb,      ks, t, g);
            ldfragA_nc(f1, Xs, rb + 16, ks, t, g);
            #pragma unroll
            for (int nt = 0; nt < 2; nt++) {
                int bi = (ks*8 + cg*2 + nt)*32 + lane;
                float2 bw = PWe[bi];
                unsigned b0 = __float_as_uint(bw.x), b1 = __float_as_uint(bw.y);
                mma8(S[0][nt], f0, b0, b1); mma8(S[1][nt], f1, b0, b1);
                bw = PWa[bi];
                b0 = __float_as_uint(bw.x); b1 = __float_as_uint(bw.y);
                mma8(T[0][nt], f0, b0, b1); mma8(T[1][nt], f1, b0, b1);
            }
        }

        float resv[2][2][4];
        float ga[4];
        #pragma unroll
        for (int q = 0; q < 4; q++)
            ga[q] = ea_w[(row0 + rb + (q>>1)*16 + (q&1)*8 + g) & 1023];
        #pragma unroll
        for (int mt = 0; mt < 2; mt++)
            #pragma unroll
            for (int nt = 0; nt < 2; nt++) {
                int c = cb + nt*8 + 2*t;
                int rA = rb + mt*16 + g;
                float2 m0 = *(const float2*)(Xs + rA*XP + c);
                float2 m1 = *(const float2*)(Xs + (rA+8)*XP + c);
                float g0 = ga[2*mt], g1 = ga[2*mt+1];
                resv[mt][nt][0] = m0.x - g0*sigf(S[mt][nt][0])*m0.x + g0*tanhfast(T[mt][nt][0]);
                resv[mt][nt][1] = m0.y - g0*sigf(S[mt][nt][1])*m0.y + g0*tanhfast(T[mt][nt][1]);
                resv[mt][nt][2] = m1.x - g1*sigf(S[mt][nt][2])*m1.x + g1*tanhfast(T[mt][nt][2]);
                resv[mt][nt][3] = m1.y - g1*sigf(S[mt][nt][3])*m1.y + g1*tanhfast(T[mt][nt][3]);
            }
        __syncthreads();
        #pragma unroll
        for (int mt = 0; mt < 2; mt++)
            #pragma unroll
            for (int nt = 0; nt < 2; nt++) {
                int c = cb + nt*8 + 2*t;
                int rA = rb + mt*16 + g;
                *(float2*)(Xs + rA*XP + c)     = make_float2(tf32f(resv[mt][nt][0]), tf32f(resv[mt][nt][1]));
                *(float2*)(Xs + (rA+8)*XP + c) = make_float2(tf32f(resv[mt][nt][2]), tf32f(resv[mt][nt][3]));
            }
        __syncthreads();

        // ---- Phase BC ----
        float R[2][2][4], Z[2][2][4], I_[2][2][4], Hh[2][2][4];
        #pragma unroll
        for (int mt = 0; mt < 2; mt++)
            #pragma unroll
            for (int nt = 0; nt < 2; nt++) {
                int c = cb + nt*8 + 2*t;
                R[mt][nt][0]=sbrz[c];    R[mt][nt][1]=sbrz[c+1];    R[mt][nt][2]=sbrz[c];    R[mt][nt][3]=sbrz[c+1];
                Z[mt][nt][0]=sbrz[64+c]; Z[mt][nt][1]=sbrz[64+c+1]; Z[mt][nt][2]=sbrz[64+c]; Z[mt][nt][3]=sbrz[64+c+1];
                I_[mt][nt][0]=sbI[c];    I_[mt][nt][1]=sbI[c+1];    I_[mt][nt][2]=sbI[c];    I_[mt][nt][3]=sbI[c+1];
                Hh[mt][nt][0]=sbH[c];    Hh[mt][nt][1]=sbH[c+1];    Hh[mt][nt][2]=sbH[c];    Hh[mt][nt][3]=sbH[c+1];
            }
        #pragma unroll
        for (int ks = 0; ks < 8; ks++) {
            unsigned f0[4], f1[4];
            ldfragA_nc(f0, Xs, rb,      ks, t, g);
            ldfragA_nc(f1, Xs, rb + 16, ks, t, g);
            #pragma unroll
            for (int nt = 0; nt < 2; nt++) {
                int bi = (ks*24 + cg*2 + nt)*32 + lane;
                float2 bw = PWih[bi];
                unsigned b0 = __float_as_uint(bw.x), b1 = __float_as_uint(bw.y);
                mma8(R[0][nt], f0, b0, b1); mma8(R[1][nt], f1, b0, b1);
                bw = PWih[bi + 256];
                b0 = __float_as_uint(bw.x); b1 = __float_as_uint(bw.y);
                mma8(Z[0][nt], f0, b0, b1); mma8(Z[1][nt], f1, b0, b1);
                bw = PWih[bi + 512];
                b0 = __float_as_uint(bw.x); b1 = __float_as_uint(bw.y);
                mma8(I_[0][nt], f0, b0, b1); mma8(I_[1][nt], f1, b0, b1);
            }
            ldfragA_nc(f0, Hs, rb,      ks, t, g);
            ldfragA_nc(f1, Hs, rb + 16, ks, t, g);
            #pragma unroll
            for (int nt = 0; nt < 2; nt++) {
                int bi = (ks*24 + cg*2 + nt)*32 + lane;
                float2 bw = PWhh[bi];
                unsigned b0 = __float_as_uint(bw.x), b1 = __float_as_uint(bw.y);
                mma8(R[0][nt], f0, b0, b1); mma8(R[1][nt], f1, b0, b1);
                bw = PWhh[bi + 256];
                b0 = __float_as_uint(bw.x); b1 = __float_as_uint(bw.y);
                mma8(Z[0][nt], f0, b0, b1); mma8(Z[1][nt], f1, b0, b1);
                bw = PWhh[bi + 512];
                b0 = __float_as_uint(bw.x); b1 = __float_as_uint(bw.y);
                mma8(Hh[0][nt], f0, b0, b1); mma8(Hh[1][nt], f1, b0, b1);
            }
        }

        float py[4] = {0.f, 0.f, 0.f, 0.f};
        #pragma unroll
        for (int mt = 0; mt < 2; mt++)
            #pragma unroll
            for (int nt = 0; nt < 2; nt++) {
                int c = cb + nt*8 + 2*t;
                int rA = rb + mt*16 + g;
                float2 h0 = *(const float2*)(Hs + rA*XP + c);
                float2 h1 = *(const float2*)(Hs + (rA+8)*XP + c);
                float wc0 = sWp[c], wc1 = sWp[c+1];
                {
                    float rr = sigf(R[mt][nt][0]), zz = sigf(Z[mt][nt][0]);
                    float nn = tanhfast(I_[mt][nt][0] + rr*Hh[mt][nt][0]);
                    py[2*mt] = fmaf((1.f-zz)*nn + zz*h0.x, wc0, py[2*mt]);
                }
                {
                    float rr = sigf(R[mt][nt][1]), zz = sigf(Z[mt][nt][1]);
                    float nn = tanhfast(I_[mt][nt][1] + rr*Hh[mt][nt][1]);
                    py[2*mt] = fmaf((1.f-zz)*nn + zz*h0.y, wc1, py[2*mt]);
                }
                {
                    float rr = sigf(R[mt][nt][2]), zz = sigf(Z[mt][nt][2]);
                    float nn = tanhfast(I_[mt][nt][2] + rr*Hh[mt][nt][2]);
                    py[2*mt+1] = fmaf((1.f-zz)*nn + zz*h1.x, wc0, py[2*mt+1]);
                }
                {
                    float rr = sigf(R[mt][nt][3]), zz = sigf(Z[mt][nt][3]);
                    float nn = tanhfast(I_[mt][nt][3] + rr*Hh[mt][nt][3]);
                    py[2*mt+1] = fmaf((1.f-zz)*nn + zz*h1.y, wc1, py[2*mt+1]);
                }
            }
        #pragma unroll
        for (int q = 0; q < 4; q++) {
            py[q] += __shfl_xor_sync(0xffffffffu, py[q], 1, 4);
            py[q] += __shfl_xor_sync(0xffffffffu, py[q], 2, 4);
        }
        if (t == 0) {
            sred[cg*128 + rb + g]      = py[0];
            sred[cg*128 + rb + 8 + g]  = py[1];
            sred[cg*128 + rb + 16 + g] = py[2];
            sred[cg*128 + rb + 24 + g] = py[3];
        }
        __syncthreads();
        if (tid < 128)
            out[row0 + tid] = sigf(sred[tid] + sred[128+tid] + sred[256+tid] + sred[384+tid] + bpv);
        __syncthreads();
    }
}

// ---------------------------------------------------------------------------
extern "C" void kernel_launch(void* const* d_in, const int* in_sizes, int n_in,
                              void* d_out, int out_size)
{
    const int*   qt  = (const int*)  d_in[1];
    const float* ht  = (const float*)d_in[2];
    const float* oh  = (const float*)d_in[3];
    const float* kc  = (const float*)d_in[4];
    const float* gr  = (const float*)d_in[5];
    const float* nw  = (const float*)d_in[6];
    const float* Ws1 = (const float*)d_in[7];
    const float* bs1 = (const float*)d_in[8];
    const float* Ws2 = (const float*)d_in[9];
    const float* bs2 = (const float*)d_in[10];
    const float* Wn1 = (const float*)d_in[11];
    const float* bn1 = (const float*)d_in[12];
    const float* Wn2 = (const float*)d_in[13];
    const float* bn2 = (const float*)d_in[14];
    const float* ea  = (const float*)d_in[15];
    const float* We  = (const float*)d_in[16];
    const float* be  = (const float*)d_in[17];
    const float* Wa  = (const float*)d_in[18];
    const float* ba  = (const float*)d_in[19];
    const float* Wih = (const float*)d_in[20];
    const float* bih = (const float*)d_in[21];
    const float* Whh = (const float*)d_in[22];
    const float* bhh = (const float*)d_in[23];
    const float* Wp  = (const float*)d_in[24];
    const float* bp  = (const float*)d_in[25];
    float* out = (float*)d_out;

    int smc = 148;
    if (cudaDeviceGetAttribute(&smc, cudaDevAttrMultiProcessorCount, 0) != cudaSuccess || smc <= 0)
        smc = 148;

    size_t smem1 = (size_t)(8704 + 17408 + 8192 + 8192 + 128 + 256) * 4;   // 171,520 B
    size_t smem2 = (size_t)51136 * 4;                                      // 204,544 B
    cudaFuncSetAttribute(f1_kernel, cudaFuncAttributeMaxDynamicSharedMemorySize, (int)smem1);
    cudaFuncSetAttribute(f2_kernel, cudaFuncAttributeMaxDynamicSharedMemorySize, (int)smem2);

    adj_kernel<<<1, 1024>>>(qt, oh, gr);
    kcbase_kernel<<<1024, 128>>>(kc, Wn1, bn1);
    f1_kernel<<<smc, 512, smem1>>>(ht, nw, Wn1, Wn2, bn2);
    selfmlp_kernel<<<256, 128>>>(qt, oh, ht, kc, Ws1, bs1, Ws2, bs2);
    f2_kernel<<<smc, 512, smem2>>>(ht, ea, We, be, Wa, ba, Wih, bih, Whh, bhh, Wp, bp, out);
}

// round 10
// speedup vs baseline: 2.0729x; 1.0496x over previous
#include <cuda_runtime.h>
#include <cstdint>
#include <math.h>

#define CC 1024
#define NROWS (256*1024)

typedef unsigned long long ull;

// Scratch (allocation-free rule: __device__ globals)
__device__ float g_adj[2*CC];
__device__ float g_kcbase[2*CC*64];
__device__ float g_mnext[(size_t)NROWS * 64];
__device__ int   g_mcnt;
__device__ int   g_mlist[65536];

__device__ __forceinline__ float clampf(float v,float lo,float hi){ return fminf(fmaxf(v,lo),hi); }
__device__ __forceinline__ float sigf(float x){ return __fdividef(1.f, 1.f + __expf(-x)); }
__device__ __forceinline__ float tanhfast(float x){
    float t = __expf(-2.f*fabsf(x));
    float r = __fdividef(1.f - t, 1.f + t);
    return copysignf(r, x);
}

// ---- tf32 helpers -----------------------------------------------------------
__device__ __forceinline__ unsigned tf32r(float f){
    unsigned u; asm("cvt.rna.tf32.f32 %0, %1;" : "=r"(u) : "f"(f)); return u;
}
__device__ __forceinline__ float tf32f(float f){ return __uint_as_float(tf32r(f)); }
__device__ __forceinline__ void mma8(float c[4], const unsigned a[4], unsigned b0, unsigned b1){
    asm volatile(
        "mma.sync.aligned.m16n8k8.row.col.f32.tf32.tf32.f32 "
        "{%0,%1,%2,%3},{%4,%5,%6,%7},{%8,%9},{%0,%1,%2,%3};"
        : "+f"(c[0]),"+f"(c[1]),"+f"(c[2]),"+f"(c[3])
        : "r"(a[0]),"r"(a[1]),"r"(a[2]),"r"(a[3]),"r"(b0),"r"(b1));
}
// Fragment-major layout: X[(rowblk*8+ks)*128 + lane*4 + reg]
//   element (r, j) -> rowblk=r>>4, ks=j>>3, lane=(r&7)*4+(j&3), reg=((j>>2)&1)*2+((r>>3)&1)
__device__ __forceinline__ void ldfragX(unsigned a[4], const float* X, int rowblk, int ks, int lane){
    float4 v = *(const float4*)(X + (((rowblk<<3) + ks)<<7) + (lane<<2));
    a[0]=__float_as_uint(v.x); a[1]=__float_as_uint(v.y);
    a[2]=__float_as_uint(v.z); a[3]=__float_as_uint(v.w);
}

// ---------------------------------------------------------------------------
// adj: mask0 has ~5 nonzeros -> compact + gather. Also resets g_mcnt.
// ---------------------------------------------------------------------------
__global__ void adj_kernel(const int* __restrict__ qt,
                           const float* __restrict__ oh,
                           const float* __restrict__ graphs)
{
    __shared__ int   s_idx[CC];
    __shared__ float s_val[CC];
    __shared__ int   s_cnt;
    __shared__ float s_sum;

    int t = threadIdx.x;
    if (t == 0) { s_cnt = 0; s_sum = 0.f; g_mcnt = 0; }
    __syncthreads();

    int q0 = qt[0];
    float m = oh[(size_t)q0 * CC + t];
    if (m != 0.f) {
        int p = atomicAdd(&s_cnt, 1);
        s_idx[p] = t; s_val[p] = m;
        atomicAdd(&s_sum, m);
    }
    __syncthreads();

    float denom = fmaxf(s_sum, 1.f);
    int nnz = s_cnt;
    for (int k = 0; k < 2; k++) {
        float acc = 0.f;
        for (int i = 0; i < nnz; i++)
            acc += s_val[i] * graphs[(size_t)k*CC*CC + (size_t)s_idx[i]*CC + t];
        g_adj[k*CC + t] = clampf(acc / denom, -5.f, 5.f);
    }
}

// ---------------------------------------------------------------------------
// maskscan: compact all masked (b,c) pairs into g_mlist
// ---------------------------------------------------------------------------
__global__ void maskscan_kernel(const int* __restrict__ qt,
                                const float* __restrict__ oh)
{
    int b = blockIdx.x;
    int q = qt[b];
    for (int c = threadIdx.x; c < CC; c += blockDim.x) {
        if (oh[(size_t)q*CC + c] > 0.5f) {
            int p = atomicAdd(&g_mcnt, 1);
            if (p < 65536) g_mlist[p] = (b << 16) | c;
        }
    }
}

// ---------------------------------------------------------------------------
// kcbase[k][c][j] = bn1[k][j] + sum_e clip(kc[c][e],±5) * Wn1[k][192+e][j]
// ---------------------------------------------------------------------------
__global__ void kcbase_kernel(const float* __restrict__ kc,
                              const float* __restrict__ Wn1,
                              const float* __restrict__ bn1)
{
    __shared__ float skc[64];
    int c = blockIdx.x;
    int tid = threadIdx.x;              // 128
    if (tid < 64) skc[tid] = clampf(kc[c*64 + tid], -5.f, 5.f);
    __syncthreads();
    int k = tid >> 6, j = tid & 63;
    float a = bn1[k*64 + j];
    const float* Wp = Wn1 + k*16384 + 12288 + j;
    #pragma unroll 8
    for (int e = 0; e < 64; e++) a = fmaf(skc[e], Wp[e*64], a);
    g_kcbase[((size_t)k*CC + c)*64 + j] = a;
}

// ---------------------------------------------------------------------------
// f1 (tensor tf32, fragment-major X/H1): 128-row tiles, 512 threads.
// ---------------------------------------------------------------------------
__global__ void __launch_bounds__(512) f1_kernel(
    const float* __restrict__ ht,  const float* __restrict__ nwp,
    const float* __restrict__ Wn1, const float* __restrict__ Wn2,
    const float* __restrict__ bn2)
{
    extern __shared__ float sm[];
    float*  Xs   = sm;                    // 8192 fragment-major tf32(clip(ht))
    float*  H1s  = Xs + 8192;             // 2*8192
    float2* PW1  = (float2*)(H1s + 16384);// 4096 f2
    float2* PW2  = PW1 + 4096;
    float*  sbn2 = (float*)(PW2 + 4096);  // 128
    float*  radj = sbn2 + 128;            // 256

    int tid = threadIdx.x;
    for (int i = tid; i < 4096; i += 512) {
        int lane = i & 31, nt = (i >> 5) & 7, ks = (i >> 8) & 7, k = i >> 11;
        int t = lane & 3, g = lane >> 2;
        int r0 = ks*8 + t, r1 = r0 + 4, c = nt*8 + g;
        float2 v;
        v.x = __uint_as_float(tf32r(Wn1[k*16384 + (128+r0)*64 + c]));
        v.y = __uint_as_float(tf32r(Wn1[k*16384 + (128+r1)*64 + c]));
        PW1[i] = v;
        v.x = __uint_as_float(tf32r(Wn2[k*4096 + r0*64 + c]));
        v.y = __uint_as_float(tf32r(Wn2[k*4096 + r1*64 + c]));
        PW2[i] = v;
    }
    if (tid < 128) sbn2[tid] = bn2[tid];
    float w = clampf(nwp[0], 0.1f, 0.9f);
    __syncthreads();

    int wid = tid >> 5, lane = tid & 31;
    int rg = wid & 3, cg = wid >> 2;
    int t = lane & 3, g = lane >> 2;
    int rb = rg * 32, cb = cg * 16;
    // res/H1 scatter offsets for this thread's C-fragments
    int q2 = (t >> 1) << 1;
    int l0 = (((g << 2) + ((2*t) & 3)) << 2) + q2;
    int l1 = (((g << 2) + ((2*t + 1)) % 4) << 2) + q2;

    for (int tile = blockIdx.x; tile < NROWS/128; tile += gridDim.x) {
        int row0 = tile << 7;
        int c0 = row0 & 1023;

        // fill Xs = tf32(clip(ht)) fragment-major
        for (int i = tid; i < 2048; i += 512) {
            int r = i >> 4, q = i & 15;
            float4 v = *(const float4*)(ht + (size_t)(row0+r)*64 + q*4);
            float* p = Xs + ((((r>>4)<<3) + (q>>1))<<7) + ((r&7)<<4) + ((q&1)<<1) + ((r>>3)&1);
            p[0]  = tf32f(clampf(v.x, -5.f, 5.f));
            p[4]  = tf32f(clampf(v.y, -5.f, 5.f));
            p[8]  = tf32f(clampf(v.z, -5.f, 5.f));
            p[12] = tf32f(clampf(v.w, -5.f, 5.f));
        }
        if (tid < 128) {
            int c = (row0 + tid) & 1023;
            radj[tid]       = g_adj[c];
            radj[128 + tid] = g_adj[CC + c];
        }
        __syncthreads();

        // ---- Stage A (both k): acc init from kcbase ----
        float A[2][2][2][4];
        #pragma unroll
        for (int k = 0; k < 2; k++) {
            const float* kcb = g_kcbase + ((size_t)k*CC + c0)*64;
            #pragma unroll
            for (int mt = 0; mt < 2; mt++)
                #pragma unroll
                for (int nt = 0; nt < 2; nt++) {
                    int c = cb + nt*8 + 2*t;
                    int rA = rb + mt*16 + g;
                    float2 v0 = *(const float2*)(kcb + rA*64 + c);
                    float2 v1 = *(const float2*)(kcb + (rA+8)*64 + c);
                    A[k][mt][nt][0]=v0.x; A[k][mt][nt][1]=v0.y;
                    A[k][mt][nt][2]=v1.x; A[k][mt][nt][3]=v1.y;
                }
        }
        #pragma unroll
        for (int ks = 0; ks < 8; ks++) {
            unsigned f0[4], f1v[4];
            ldfragX(f0,  Xs, rg*2,     ks, lane);
            ldfragX(f1v, Xs, rg*2 + 1, ks, lane);
            #pragma unroll
            for (int k = 0; k < 2; k++)
                #pragma unroll
                for (int nt = 0; nt < 2; nt++) {
                    int bi = ((k*8 + ks)*8 + cg*2 + nt)*32 + lane;
                    float2 bw = PW1[bi];
                    unsigned b0 = __float_as_uint(bw.x), b1 = __float_as_uint(bw.y);
                    mma8(A[k][0][nt], f0,  b0, b1);
                    mma8(A[k][1][nt], f1v, b0, b1);
                }
        }
        // relu + tf32 -> H1s fragment-major
        #pragma unroll
        for (int k = 0; k < 2; k++) {
            float* Hk = H1s + k*8192;
            #pragma unroll
            for (int mt = 0; mt < 2; mt++)
                #pragma unroll
                for (int nt = 0; nt < 2; nt++) {
                    float* base = Hk + ((((rg*2+mt)<<3) + (cg*2+nt))<<7);
                    base[l0]     = tf32f(fmaxf(A[k][mt][nt][0], 0.f));
                    base[l1]     = tf32f(fmaxf(A[k][mt][nt][1], 0.f));
                    base[l0 + 1] = tf32f(fmaxf(A[k][mt][nt][2], 0.f));
                    base[l1 + 1] = tf32f(fmaxf(A[k][mt][nt][3], 0.f));
                }
        }
        __syncthreads();

        // ---- Stage B (both k) ----
        float B[2][2][2][4];
        #pragma unroll
        for (int k = 0; k < 2; k++)
            #pragma unroll
            for (int mt = 0; mt < 2; mt++)
                #pragma unroll
                for (int nt = 0; nt < 2; nt++) {
                    int c = cb + nt*8 + 2*t;
                    float b0 = sbn2[k*64 + c], b1 = sbn2[k*64 + c + 1];
                    B[k][mt][nt][0]=b0; B[k][mt][nt][1]=b1; B[k][mt][nt][2]=b0; B[k][mt][nt][3]=b1;
                }
        #pragma unroll
        for (int ks = 0; ks < 8; ks++) {
            unsigned e0[4], e1[4], e2[4], e3[4];
            ldfragX(e0, H1s,        rg*2,     ks, lane);
            ldfragX(e1, H1s,        rg*2 + 1, ks, lane);
            ldfragX(e2, H1s + 8192, rg*2,     ks, lane);
            ldfragX(e3, H1s + 8192, rg*2 + 1, ks, lane);
            #pragma unroll
            for (int nt = 0; nt < 2; nt++) {
                int bi0 = ((0*8 + ks)*8 + cg*2 + nt)*32 + lane;
                int bi1 = ((1*8 + ks)*8 + cg*2 + nt)*32 + lane;
                float2 bw = PW2[bi0];
                unsigned b0 = __float_as_uint(bw.x), b1 = __float_as_uint(bw.y);
                mma8(B[0][0][nt], e0, b0, b1); mma8(B[0][1][nt], e1, b0, b1);
                bw = PW2[bi1];
                b0 = __float_as_uint(bw.x); b1 = __float_as_uint(bw.y);
                mma8(B[1][0][nt], e2, b0, b1); mma8(B[1][1][nt], e3, b0, b1);
            }
        }

        // fold nf + write ALL rows (tf32-rounded), row-major global
        #pragma unroll
        for (int mt = 0; mt < 2; mt++) {
            int rA = rb + mt*16 + g;
            float a00 = radj[rA],       a01 = radj[rA + 8];
            float a10 = radj[128 + rA], a11 = radj[128 + rA + 8];
            #pragma unroll
            for (int nt = 0; nt < 2; nt++) {
                int c = cb + nt*8 + 2*t;
                float n0 = clampf(a00 * clampf(B[0][mt][nt][0], 0.f, 5.f), -5.f, 5.f);
                float n1 = clampf(a00 * clampf(B[0][mt][nt][1], 0.f, 5.f), -5.f, 5.f);
                float n2 = clampf(a01 * clampf(B[0][mt][nt][2], 0.f, 5.f), -5.f, 5.f);
                float n3 = clampf(a01 * clampf(B[0][mt][nt][3], 0.f, 5.f), -5.f, 5.f);
                float u0 = a10 * clampf(B[1][mt][nt][0], 0.f, 5.f);
                float u1 = a10 * clampf(B[1][mt][nt][1], 0.f, 5.f);
                float u2 = a11 * clampf(B[1][mt][nt][2], 0.f, 5.f);
                float u3 = a11 * clampf(B[1][mt][nt][3], 0.f, 5.f);
                n0 = clampf(w*n0 + (1.f-w)*u0, -5.f, 5.f);
                n1 = clampf(w*n1 + (1.f-w)*u1, -5.f, 5.f);
                n2 = clampf(w*n2 + (1.f-w)*u2, -5.f, 5.f);
                n3 = clampf(w*n3 + (1.f-w)*u3, -5.f, 5.f);
                *(float2*)(&g_mnext[(size_t)(row0+rA)*64 + c])   = make_float2(tf32f(n0), tf32f(n1));
                *(float2*)(&g_mnext[(size_t)(row0+rA+8)*64 + c]) = make_float2(tf32f(n2), tf32f(n3));
            }
        }
        __syncthreads();
    }
}

// ---------------------------------------------------------------------------
// selfmlp fix: one masked (b,c) pair per block, parallel across SMs.
// ---------------------------------------------------------------------------
__global__ void __launch_bounds__(128) selfmlp_kernel(
    const float* __restrict__ ht, const float* __restrict__ kc,
    const float* __restrict__ Ws1, const float* __restrict__ bs1,
    const float* __restrict__ Ws2, const float* __restrict__ bs2)
{
    __shared__ float xr[128];
    __shared__ float hb[64];
    int tid = threadIdx.x;
    int cnt = g_mcnt; if (cnt > 65536) cnt = 65536;

    for (int i = blockIdx.x; i < cnt; i += gridDim.x) {
        int pc = g_mlist[i];
        int b = pc >> 16, c = pc & 0xffff;
        size_t gid = (size_t)b*CC + c;
        xr[tid] = (tid < 64) ? ht[gid*64 + tid] : kc[c*64 + tid - 64];
        __syncthreads();
        if (tid < 64) {
            float a = bs1[tid];
            #pragma unroll 8
            for (int j = 0; j < 128; j++) a = fmaf(xr[j], Ws1[j*64 + tid], a);
            hb[tid] = fmaxf(a, 0.f);
        }
        __syncthreads();
        if (tid < 64) {
            float a = bs2[tid];
            #pragma unroll 8
            for (int j = 0; j < 64; j++) a = fmaf(hb[j], Ws2[j*64 + tid], a);
            g_mnext[gid*64 + tid] = tf32f(clampf(a, 0.f, 10.f));
        }
        __syncthreads();
    }
}

// ---------------------------------------------------------------------------
// f2 (tensor tf32, fragment-major Xs/Hs)
// ---------------------------------------------------------------------------
__global__ void __launch_bounds__(512) f2_kernel(
    const float* __restrict__ ht,  const float* __restrict__ ea_w,
    const float* __restrict__ We,  const float* __restrict__ be,
    const float* __restrict__ Wa,  const float* __restrict__ ba,
    const float* __restrict__ Wih, const float* __restrict__ bih,
    const float* __restrict__ Whh, const float* __restrict__ bhh,
    const float* __restrict__ Wp,  const float* __restrict__ bp,
    float* __restrict__ out)
{
    extern __shared__ float sm[];
    float*  Xs   = sm;                       // 8192 (m tf32, then res tf32) frag-major
    float*  Hs   = Xs + 8192;                // 8192 (ht tf32) frag-major
    float2* PWe  = (float2*)(Hs + 8192);     // 2048 f2
    float2* PWa  = PWe + 2048;
    float2* PWih = PWa + 2048;               // 6144 f2
    float2* PWhh = PWih + 6144;
    float*  sbe  = (float*)(PWhh + 6144);
    float*  sba  = sbe + 64;
    float*  sbrz = sba + 64;
    float*  sbI  = sbrz + 128;
    float*  sbH  = sbI + 64;
    float*  sWp  = sbH + 64;
    float*  sred = sWp + 64;                 // 512

    int tid = threadIdx.x;

    for (int i = tid; i < 2048; i += 512) {
        int lane = i & 31, nt = (i >> 5) & 7, ks = i >> 8;
        int t = lane & 3, g = lane >> 2;
        int r0 = ks*8 + t, r1 = r0 + 4, c = nt*8 + g;
        float2 v;
        v.x = __uint_as_float(tf32r(We[r0*64 + c]));
        v.y = __uint_as_float(tf32r(We[r1*64 + c]));
        PWe[i] = v;
        v.x = __uint_as_float(tf32r(Wa[r0*64 + c]));
        v.y = __uint_as_float(tf32r(Wa[r1*64 + c]));
        PWa[i] = v;
    }
    for (int i = tid; i < 6144; i += 512) {
        int lane = i & 31; int rest = i >> 5; int nt = rest % 24, ks = rest / 24;
        int t = lane & 3, g = lane >> 2;
        int r0 = ks*8 + t, r1 = r0 + 4, c = nt*8 + g;
        float2 v;
        v.x = __uint_as_float(tf32r(Wih[r0*192 + c]));
        v.y = __uint_as_float(tf32r(Wih[r1*192 + c]));
        PWih[i] = v;
        v.x = __uint_as_float(tf32r(Whh[r0*192 + c]));
        v.y = __uint_as_float(tf32r(Whh[r1*192 + c]));
        PWhh[i] = v;
    }
    if (tid < 64) {
        sbe[tid] = be[tid]; sba[tid] = ba[tid]; sWp[tid] = Wp[tid];
        sbI[tid] = bih[128 + tid]; sbH[tid] = bhh[128 + tid];
    }
    if (tid < 128) sbrz[tid] = bih[tid] + bhh[tid];
    float bpv = bp[0];
    __syncthreads();

    int wid = tid >> 5, lane = tid & 31;
    int rg = wid & 3, cg = wid >> 2;
    int t = lane & 3, g = lane >> 2;
    int rb = rg * 32, cb = cg * 16;
    int q2 = (t >> 1) << 1;
    int l0 = (((g << 2) + ((2*t) & 3)) << 2) + q2;
    int l1 = (((g << 2) + ((2*t + 1)) % 4) << 2) + q2;

    for (int tile = blockIdx.x; tile < NROWS/128; tile += gridDim.x) {
        int row0 = tile << 7;

        for (int i = tid; i < 2048; i += 512) {
            int r = i >> 4, q = i & 15;
            float4 m4 = *(const float4*)(g_mnext + (size_t)(row0+r)*64 + q*4);  // already tf32
            float4 h4 = *(const float4*)(ht      + (size_t)(row0+r)*64 + q*4);
            int off = ((((r>>4)<<3) + (q>>1))<<7) + ((r&7)<<4) + ((q&1)<<1) + ((r>>3)&1);
            float* px = Xs + off;
            px[0] = m4.x; px[4] = m4.y; px[8] = m4.z; px[12] = m4.w;
            float* ph = Hs + off;
            ph[0] = tf32f(h4.x); ph[4] = tf32f(h4.y); ph[8] = tf32f(h4.z); ph[12] = tf32f(h4.w);
        }
        __syncthreads();

        // ---- Phase A ----
        float S[2][2][4], T[2][2][4];
        #pragma unroll
        for (int mt = 0; mt < 2; mt++)
            #pragma unroll
            for (int nt = 0; nt < 2; nt++) {
                int c = cb + nt*8 + 2*t;
                S[mt][nt][0]=sbe[c]; S[mt][nt][1]=sbe[c+1]; S[mt][nt][2]=sbe[c]; S[mt][nt][3]=sbe[c+1];
                T[mt][nt][0]=sba[c]; T[mt][nt][1]=sba[c+1]; T[mt][nt][2]=sba[c]; T[mt][nt][3]=sba[c+1];
            }
        #pragma unroll
        for (int ks = 0; ks < 8; ks++) {
            unsigned f0[4], f1[4];
            ldfragX(f0, Xs, rg*2,     ks, lane);
            ldfragX(f1, Xs, rg*2 + 1, ks, lane);
            #pragma unroll
            for (int nt = 0; nt < 2; nt++) {
                int bi = (ks*8 + cg*2 + nt)*32 + lane;
                float2 bw = PWe[bi];
                unsigned b0 = __float_as_uint(bw.x), b1 = __float_as_uint(bw.y);
                mma8(S[0][nt], f0, b0, b1); mma8(S[1][nt], f1, b0, b1);
                bw = PWa[bi];
                b0 = __float_as_uint(bw.x); b1 = __float_as_uint(bw.y);
                mma8(T[0][nt], f0, b0, b1); mma8(T[1][nt], f1, b0, b1);
            }
        }

        float resv[2][2][4];
        float ga[4];
        #pragma unroll
        for (int q = 0; q < 4; q++)
            ga[q] = ea_w[(row0 + rb + (q>>1)*16 + (q&1)*8 + g) & 1023];
        #pragma unroll
        for (int mt = 0; mt < 2; mt++)
            #pragma unroll
            for (int nt = 0; nt < 2; nt++) {
                const float* base = Xs + ((((rg*2+mt)<<3) + (cg*2+nt))<<7);
                float m00 = base[l0], m01 = base[l1];
                float m10 = base[l0 + 1], m11 = base[l1 + 1];
                float g0 = ga[2*mt], g1 = ga[2*mt+1];
                resv[mt][nt][0] = m00 - g0*sigf(S[mt][nt][0])*m00 + g0*tanhfast(T[mt][nt][0]);
                resv[mt][nt][1] = m01 - g0*sigf(S[mt][nt][1])*m01 + g0*tanhfast(T[mt][nt][1]);
                resv[mt][nt][2] = m10 - g1*sigf(S[mt][nt][2])*m10 + g1*tanhfast(T[mt][nt][2]);
                resv[mt][nt][3] = m11 - g1*sigf(S[mt][nt][3])*m11 + g1*tanhfast(T[mt][nt][3]);
            }
        __syncthreads();
        #pragma unroll
        for (int mt = 0; mt < 2; mt++)
            #pragma unroll
            for (int nt = 0; nt < 2; nt++) {
                float* base = Xs + ((((rg*2+mt)<<3) + (cg*2+nt))<<7);
                base[l0]     = tf32f(resv[mt][nt][0]);
                base[l1]     = tf32f(resv[mt][nt][1]);
                base[l0 + 1] = tf32f(resv[mt][nt][2]);
                base[l1 + 1] = tf32f(resv[mt][nt][3]);
            }
        __syncthreads();

        // ---- Phase BC ----
        float R[2][2][4], Z[2][2][4], I_[2][2][4], Hh[2][2][4];
        #pragma unroll
        for (int mt = 0; mt < 2; mt++)
            #pragma unroll
            for (int nt = 0; nt < 2; nt++) {
                int c = cb + nt*8 + 2*t;
                R[mt][nt][0]=sbrz[c];    R[mt][nt][1]=sbrz[c+1];    R[mt][nt][2]=sbrz[c];    R[mt][nt][3]=sbrz[c+1];
                Z[mt][nt][0]=sbrz[64+c]; Z[mt][nt][1]=sbrz[64+c+1]; Z[mt][nt][2]=sbrz[64+c]; Z[mt][nt][3]=sbrz[64+c+1];
                I_[mt][nt][0]=sbI[c];    I_[mt][nt][1]=sbI[c+1];    I_[mt][nt][2]=sbI[c];    I_[mt][nt][3]=sbI[c+1];
                Hh[mt][nt][0]=sbH[c];    Hh[mt][nt][1]=sbH[c+1];    Hh[mt][nt][2]=sbH[c];    Hh[mt][nt][3]=sbH[c+1];
            }
        #pragma unroll
        for (int ks = 0; ks < 8; ks++) {
            unsigned f0[4], f1[4];
            ldfragX(f0, Xs, rg*2,     ks, lane);
            ldfragX(f1, Xs, rg*2 + 1, ks, lane);
            #pragma unroll
            for (int nt = 0; nt < 2; nt++) {
                int bi = (ks*24 + cg*2 + nt)*32 + lane;
                float2 bw = PWih[bi];
                unsigned b0 = __float_as_uint(bw.x), b1 = __float_as_uint(bw.y);
                mma8(R[0][nt], f0, b0, b1); mma8(R[1][nt], f1, b0, b1);
                bw = PWih[bi + 256];
                b0 = __float_as_uint(bw.x); b1 = __float_as_uint(bw.y);
                mma8(Z[0][nt], f0, b0, b1); mma8(Z[1][nt], f1, b0, b1);
                bw = PWih[bi + 512];
                b0 = __float_as_uint(bw.x); b1 = __float_as_uint(bw.y);
                mma8(I_[0][nt], f0, b0, b1); mma8(I_[1][nt], f1, b0, b1);
            }
            ldfragX(f0, Hs, rg*2,     ks, lane);
            ldfragX(f1, Hs, rg*2 + 1, ks, lane);
            #pragma unroll
            for (int nt = 0; nt < 2; nt++) {
                int bi = (ks*24 + cg*2 + nt)*32 + lane;
                float2 bw = PWhh[bi];
                unsigned b0 = __float_as_uint(bw.x), b1 = __float_as_uint(bw.y);
                mma8(R[0][nt], f0, b0, b1); mma8(R[1][nt], f1, b0, b1);
                bw = PWhh[bi + 256];
                b0 = __float_as_uint(bw.x); b1 = __float_as_uint(bw.y);
                mma8(Z[0][nt], f0, b0, b1); mma8(Z[1][nt], f1, b0, b1);
                bw = PWhh[bi + 512];
                b0 = __float_as_uint(bw.x); b1 = __float_as_uint(bw.y);
                mma8(Hh[0][nt], f0, b0, b1); mma8(Hh[1][nt], f1, b0, b1);
            }
        }

        float py[4] = {0.f, 0.f, 0.f, 0.f};
        #pragma unroll
        for (int mt = 0; mt < 2; mt++)
            #pragma unroll
            for (int nt = 0; nt < 2; nt++) {
                int c = cb + nt*8 + 2*t;
                const float* hbase = Hs + ((((rg*2+mt)<<3) + (cg*2+nt))<<7);
                float h00 = hbase[l0], h01 = hbase[l1];
                float h10 = hbase[l0 + 1], h11 = hbase[l1 + 1];
                float wc0 = sWp[c], wc1 = sWp[c+1];
                {
                    float rr = sigf(R[mt][nt][0]), zz = sigf(Z[mt][nt][0]);
                    float nn = tanhfast(I_[mt][nt][0] + rr*Hh[mt][nt][0]);
                    py[2*mt] = fmaf((1.f-zz)*nn + zz*h00, wc0, py[2*mt]);
                }
                {
                    float rr = sigf(R[mt][nt][1]), zz = sigf(Z[mt][nt][1]);
                    float nn = tanhfast(I_[mt][nt][1] + rr*Hh[mt][nt][1]);
                    py[2*mt] = fmaf((1.f-zz)*nn + zz*h01, wc1, py[2*mt]);
                }
                {
                    float rr = sigf(R[mt][nt][2]), zz = sigf(Z[mt][nt][2]);
                    float nn = tanhfast(I_[mt][nt][2] + rr*Hh[mt][nt][2]);
                    py[2*mt+1] = fmaf((1.f-zz)*nn + zz*h10, wc0, py[2*mt+1]);
                }
                {
                    float rr = sigf(R[mt][nt][3]), zz = sigf(Z[mt][nt][3]);
                    float nn = tanhfast(I_[mt][nt][3] + rr*Hh[mt][nt][3]);
                    py[2*mt+1] = fmaf((1.f-zz)*nn + zz*h11, wc1, py[2*mt+1]);
                }
            }
        #pragma unroll
        for (int q = 0; q < 4; q++) {
            py[q] += __shfl_xor_sync(0xffffffffu, py[q], 1, 4);
            py[q] += __shfl_xor_sync(0xffffffffu, py[q], 2, 4);
        }
        if (t == 0) {
            sred[cg*128 + rb + g]      = py[0];
            sred[cg*128 + rb + 8 + g]  = py[1];
            sred[cg*128 + rb + 16 + g] = py[2];
            sred[cg*128 + rb + 24 + g] = py[3];
        }
        __syncthreads();
        if (tid < 128)
            out[row0 + tid] = sigf(sred[tid] + sred[128+tid] + sred[256+tid] + sred[384+tid] + bpv);
        __syncthreads();
    }
}

// ---------------------------------------------------------------------------
extern "C" void kernel_launch(void* const* d_in, const int* in_sizes, int n_in,
                              void* d_out, int out_size)
{
    const int*   qt  = (const int*)  d_in[1];
    const float* ht  = (const float*)d_in[2];
    const float* oh  = (const float*)d_in[3];
    const float* kc  = (const float*)d_in[4];
    const float* gr  = (const float*)d_in[5];
    const float* nw  = (const float*)d_in[6];
    const float* Ws1 = (const float*)d_in[7];
    const float* bs1 = (const float*)d_in[8];
    const float* Ws2 = (const float*)d_in[9];
    const float* bs2 = (const float*)d_in[10];
    const float* Wn1 = (const float*)d_in[11];
    const float* bn1 = (const float*)d_in[12];
    const float* Wn2 = (const float*)d_in[13];
    const float* bn2 = (const float*)d_in[14];
    const float* ea  = (const float*)d_in[15];
    const float* We  = (const float*)d_in[16];
    const float* be  = (const float*)d_in[17];
    const float* Wa  = (const float*)d_in[18];
    const float* ba  = (const float*)d_in[19];
    const float* Wih = (const float*)d_in[20];
    const float* bih = (const float*)d_in[21];
    const float* Whh = (const float*)d_in[22];
    const float* bhh = (const float*)d_in[23];
    const float* Wp  = (const float*)d_in[24];
    const float* bp  = (const float*)d_in[25];
    float* out = (float*)d_out;

    int smc = 148;
    if (cudaDeviceGetAttribute(&smc, cudaDevAttrMultiProcessorCount, 0) != cudaSuccess || smc <= 0)
        smc = 148;

    size_t smem1 = (size_t)(8192 + 16384 + 8192 + 8192 + 128 + 256) * 4;   // 165,376 B
    size_t smem2 = (size_t)(8192 + 8192 + 4096 + 4096 + 12288 + 12288 + 64+64+128+64+64+64+512) * 4;  // 200,448 B
    cudaFuncSetAttribute(f1_kernel, cudaFuncAttributeMaxDynamicSharedMemorySize, (int)smem1);
    cudaFuncSetAttribute(f2_kernel, cudaFuncAttributeMaxDynamicSharedMemorySize, (int)smem2);

    adj_kernel<<<1, 1024>>>(qt, oh, gr);
    maskscan_kernel<<<256, 256>>>(qt, oh);
    kcbase_kernel<<<1024, 128>>>(kc, Wn1, bn1);
    f1_kernel<<<smc, 512, smem1>>>(ht, nw, Wn1, Wn2, bn2);
    selfmlp_kernel<<<2048, 128>>>(ht, kc, Ws1, bs1, Ws2, bs2);
    f2_kernel<<<smc, 512, smem2>>>(ht, ea, We, be, Wa, ba, Wih, bih, Whh, bhh, Wp, bp, out);
}